// round 12
// baseline (speedup 1.0000x reference)
#include <cuda_runtime.h>
#include <cuda_fp16.h>
#include <cstdint>

// ---------------- problem constants ----------------
#define BATCH 64
#define NTOK  197
#define HEADS 12
#define HDIM  64
#define CDIM  768
#define CK    2304
#define MROWS (BATCH*NTOK) // 12608
#define NRD   732
#define NW    50
#define BHT   (BATCH*HEADS)

// ---------------- device scratch (cudaMalloc is banned) -------------
__device__ float              g_qkv[(size_t)MROWS * CK];
__device__ float              g_att[(size_t)MROWS * CDIM];
__device__ float              g_sq[BHT];
__device__ float              g_sk[BHT];
__device__ unsigned long long g_qb[BHT * NTOK];
__device__ unsigned long long g_kb[BHT * NTOK];
__device__ unsigned int       g_vT[(size_t)BHT * HDIM * NW];

// ---------------- small helpers ----------------
__device__ __forceinline__ int dp4a_us(unsigned int a, unsigned int b, int c) {
    int d; asm("dp4a.u32.s32 %0, %1, %2, %3;" : "=r"(d) : "r"(a), "r"(b), "r"(c));
    return d;
}
__device__ __forceinline__ void mma_f16(float* c, const uint32_t* a, const uint32_t* b) {
    asm volatile(
        "mma.sync.aligned.m16n8k16.row.col.f32.f16.f16.f32 "
        "{%0,%1,%2,%3}, {%4,%5,%6,%7}, {%8,%9}, {%0,%1,%2,%3};"
        : "+f"(c[0]), "+f"(c[1]), "+f"(c[2]), "+f"(c[3])
        : "r"(a[0]), "r"(a[1]), "r"(a[2]), "r"(a[3]), "r"(b[0]), "r"(b[1]));
}
// Exponent-compensated fp16 2-way splits (all terms normal-range; no
// subnormal-flush hazard):
//   A (x ~ O(1)):   x    = a0 + a1*2^-11 + O(2^-22 x)
//   W (w ~ 0.02):   32*w = b0 + b1*2^-11 + O(2^-22 *32w)
// so x*w = 2^-5*a0b0 + 2^-16*(a0b1 + a1b0) + O(2^-22 xw)  [P=3, 11 dropped]
__device__ __forceinline__ void hsplitA(float x, uint16_t& s0, uint16_t& s1) {
    __half h0 = __float2half_rn(x);
    __half h1 = __float2half_rn((x - __half2float(h0)) * 2048.0f);
    s0 = *reinterpret_cast<uint16_t*>(&h0);
    s1 = *reinterpret_cast<uint16_t*>(&h1);
}
__device__ __forceinline__ void hsplitB(float w, uint16_t& s0, uint16_t& s1) {
    float ws = w * 32.0f;
    __half h0 = __float2half_rn(ws);
    __half h1 = __float2half_rn((ws - __half2float(h0)) * 2048.0f);
    s0 = *reinterpret_cast<uint16_t*>(&h0);
    s1 = *reinterpret_cast<uint16_t*>(&h1);
}

#define SC_HH 0.03125f                    // 2^-5
#define SC_C  1.52587890625e-05f          // 2^-16

// ====== compensated-fp16 mma.sync GEMM, fp32 register drain (R11 scheme) ====
// C[M,N] = A[M,768] @ W[N,768]^T (+bias), leading dim ldc.  P=3 everywhere:
// products 00 (2^-5) and 01+10 (2^-16) into two zero-init fragments, drained
// to fp32 registers with exact-pow2 FFMAs each k-tile.  The dropped 11 term
// (~2^-22|xw|) is handled for the sign-critical QK path by the exact fp32
// repair in pack_kernel (see below).
#define GK      768
#define TBM     128
#define TBN     128
#define TBK     16
#define KT      (GK / TBK)          // 48
#define RPAD    12                  // u32 per smem row (8 data + 4 pad)
#define TILEU   (128 * RPAD)        // u32 per tile
#define GSMEM   (2 * 2 * 2 * TILEU * 4)   // 49,152 B

__global__ void __launch_bounds__(256, 1) gemm_f16c(
    const float* __restrict__ A, const float* __restrict__ W,
    const float* __restrict__ bias, float* __restrict__ C,
    int M, int ldc)
{
    extern __shared__ uint32_t smu[];
    auto tbase = [&](int buf, int mat, int t) -> uint32_t* {
        return smu + (size_t)(((buf * 2 + mat) * 2) + t) * TILEU;
    };

    const int tid  = threadIdx.x;
    const int wid  = tid >> 5;
    const int lane = tid & 31;
    const int gq   = lane >> 2;             // 0..7
    const int tq   = lane & 3;              // 0..3
    const int bm = blockIdx.y * TBM;
    const int bn = blockIdx.x * TBN;
    const int wm = (wid >> 2) * 64;
    const int wn = (wid & 3) * 32;

    // ---- producer mapping: 1 row x 8 k-floats per matrix per thread ----
    const int prow = tid >> 1;              // 0..127
    const int kseg = tid & 1;               // 0/1 -> k offset 0/8
    int arow = bm + prow; if (arow >= M) arow = M - 1;
    const float* gA = A + (size_t)arow * GK + kseg * 8;
    const float* gW = W + (size_t)(bn + prow) * GK + kseg * 8;
    const int off = prow * RPAD + kseg * 4; // u32 index (16B aligned)

    float4 stage[2][4];   // [set][A.lo4, A.hi4, W.lo4, W.hi4]; stage s -> set s&1

    auto ldg_stage = [&](int set, int kt) {
        const int kof = kt * TBK;
        stage[set][0] = *(const float4*)(gA + kof);
        stage[set][1] = *(const float4*)(gA + kof + 4);
        stage[set][2] = *(const float4*)(gW + kof);
        stage[set][3] = *(const float4*)(gW + kof + 4);
    };
    auto pack8 = [&](float4 v0, float4 v1, int buf, int mat) {
        float xs[8] = {v0.x, v0.y, v0.z, v0.w, v1.x, v1.y, v1.z, v1.w};
        uint16_t s0[8], s1[8];
        #pragma unroll
        for (int i = 0; i < 8; i++) {
            if (mat == 0) hsplitA(xs[i], s0[i], s1[i]);
            else          hsplitB(xs[i], s0[i], s1[i]);
        }
        uint4 t0, t1;
        t0.x = (uint32_t)s0[0] | ((uint32_t)s0[1] << 16);
        t0.y = (uint32_t)s0[2] | ((uint32_t)s0[3] << 16);
        t0.z = (uint32_t)s0[4] | ((uint32_t)s0[5] << 16);
        t0.w = (uint32_t)s0[6] | ((uint32_t)s0[7] << 16);
        t1.x = (uint32_t)s1[0] | ((uint32_t)s1[1] << 16);
        t1.y = (uint32_t)s1[2] | ((uint32_t)s1[3] << 16);
        t1.z = (uint32_t)s1[4] | ((uint32_t)s1[5] << 16);
        t1.w = (uint32_t)s1[6] | ((uint32_t)s1[7] << 16);
        *(uint4*)(tbase(buf, mat, 0) + off) = t0;
        *(uint4*)(tbase(buf, mat, 1) + off) = t1;
    };
    auto convert_store = [&](int set, int buf) {
        pack8(stage[set][0], stage[set][1], buf, 0);
        pack8(stage[set][2], stage[set][3], buf, 1);
    };

    float acc[4][4][4];
    #pragma unroll
    for (int i = 0; i < 4; i++)
        #pragma unroll
        for (int j = 0; j < 4; j++)
            #pragma unroll
            for (int r = 0; r < 4; r++) acc[i][j][r] = 0.f;

    // ---- prologue: stage0 -> set0 -> buf0; stage1 -> set1 ----
    ldg_stage(0, 0);
    convert_store(0, 0);
    ldg_stage(1, 1);
    __syncthreads();

    for (int kt = 0; kt < KT; ++kt) {
        const int cset = (kt + 1) & 1;                    // stage kt+1 lives in set (kt+1)&1
        if (kt + 1 < KT) convert_store(cset, (kt + 1) & 1);
        if (kt + 2 < KT) ldg_stage(cset ^ 1, kt + 2);     // stage kt+2 -> set (kt+2)&1

        const int buf = kt & 1;
        const uint32_t* at[2]; const uint32_t* bt[2];
        #pragma unroll
        for (int t = 0; t < 2; ++t) {
            at[t] = tbase(buf, 0, t) + (wm + gq) * RPAD;
            bt[t] = tbase(buf, 1, t) + (wn + gq) * RPAD;
        }

        // B fragments: 2 terms x 4 n-tiles
        uint32_t bf[2][4][2];
        #pragma unroll
        for (int t = 0; t < 2; ++t)
            #pragma unroll
            for (int nt = 0; nt < 4; ++nt) {
                const uint32_t* bp = bt[t] + nt * 8 * RPAD + tq;
                bf[t][nt][0] = bp[0];
                bf[t][nt][1] = bp[4];
            }
        #pragma unroll
        for (int mt = 0; mt < 4; ++mt) {
            uint32_t af[2][4];
            #pragma unroll
            for (int t = 0; t < 2; ++t) {
                const uint32_t* ap = at[t] + mt * 16 * RPAD + tq;
                af[t][0] = ap[0];
                af[t][1] = ap[8 * RPAD];
                af[t][2] = ap[4];
                af[t][3] = ap[8 * RPAD + 4];
            }
            #pragma unroll
            for (int nt = 0; nt < 4; ++nt) {
                // zero-init fragments: partials stay small, so the mma C-path's
                // reduced-precision accumulate only rounds small values.
                float dh[4] = {0.f, 0.f, 0.f, 0.f};
                mma_f16(dh, af[0], bf[0][nt]);            // 00  (scale 2^-5)
                float dc[4] = {0.f, 0.f, 0.f, 0.f};
                mma_f16(dc, af[0], bf[1][nt]);            // 01  (scale 2^-16)
                mma_f16(dc, af[1], bf[0][nt]);            // 10  (scale 2^-16)
                #pragma unroll
                for (int r = 0; r < 4; ++r) {
                    float a = acc[mt][nt][r];
                    a = fmaf(dh[r], SC_HH, a);            // exact-pow2 drains
                    a = fmaf(dc[r], SC_C, a);
                    acc[mt][nt][r] = a;
                }
            }
        }
        __syncthreads();
    }

    // ---- epilogue ----
    #pragma unroll
    for (int mt = 0; mt < 4; ++mt) {
        int r0 = bm + wm + mt * 16 + gq;
        int r1 = r0 + 8;
        #pragma unroll
        for (int nt = 0; nt < 4; ++nt) {
            int c = bn + wn + nt * 8 + tq * 2;
            float b0 = bias ? bias[c]     : 0.f;
            float b1 = bias ? bias[c + 1] : 0.f;
            if (r0 < M) {
                float2 v; v.x = acc[mt][nt][0] + b0; v.y = acc[mt][nt][1] + b1;
                *(float2*)(C + (size_t)r0 * ldc + c) = v;
            }
            if (r1 < M) {
                float2 v; v.x = acc[mt][nt][2] + b0; v.y = acc[mt][nt][3] + b1;
                *(float2*)(C + (size_t)r1 * ldc + c) = v;
            }
        }
    }
}

// ---------------- per-(b,h) |q| / |k| mean scales ----------------
__global__ __launch_bounds__(256) void scales_kernel(const float* __restrict__ qkv)
{
    __shared__ float red[256];
    const int which = blockIdx.x & 1;
    const int bh    = blockIdx.x >> 1;
    const int b = bh / HEADS, h = bh % HEADS;
    const float* base = qkv + (size_t)b * NTOK * CK + which * CDIM + h * HDIM;

    float s = 0.f;
    for (int i = threadIdx.x; i < NTOK * HDIM; i += 256) {
        int n = i >> 6, dd = i & 63;
        s += fabsf(base[(size_t)n * CK + dd]);
    }
    red[threadIdx.x] = s; __syncthreads();
    for (int o = 128; o; o >>= 1) {
        if (threadIdx.x < o) red[threadIdx.x] += red[threadIdx.x + o];
        __syncthreads();
    }
    if (threadIdx.x == 0) {
        float v = red[0] / 12608.0f;
        if (which) g_sk[bh] = v; else g_sq[bh] = v;
    }
}

// ---------------- pack: sign bits (with exact fp32 repair), int8 v ---------
// REPAIR: q/k elements with |value| < 1e-4 (P=3 GEMM error is ~1.3e-7, so
// only these can sign-flip) are recomputed exactly in fp32. ~3k dots total.
#define REPAIR_TH 1e-4f
__device__ __forceinline__ float exact_dot768(const float* __restrict__ xr,
                                              const float* __restrict__ wr) {
    float s = 0.f;
    #pragma unroll 8
    for (int i = 0; i < GK; i++) s = fmaf(xr[i], wr[i], s);
    return s;
}

__global__ __launch_bounds__(256) void pack_kernel(
    const float* __restrict__ qkv,
    const float* __restrict__ x, const float* __restrict__ qkv_w)
{
    const int bh = blockIdx.x;
    const int b = bh / HEADS, h = bh % HEADS;
    const size_t rowbase = (size_t)b * NTOK * CK + h * HDIM;
    const float* qb_ = qkv + rowbase;
    const float* kb_ = qkv + rowbase + CDIM;
    const float* vb_ = qkv + rowbase + 2 * CDIM;

    for (int n = threadIdx.x; n < NTOK; n += 256) {
        const float* qr = qb_ + (size_t)n * CK;
        const float* kr = kb_ + (size_t)n * CK;
        const float* xrow = x + (size_t)(b * NTOK + n) * GK;
        unsigned long long qm = 0ull, km = 0ull;
        #pragma unroll
        for (int c4 = 0; c4 < 16; c4++) {
            float qe[4], ke[4];
            *(float4*)qe = *(const float4*)(qr + c4 * 4);
            *(float4*)ke = *(const float4*)(kr + c4 * 4);
            #pragma unroll
            for (int j = 0; j < 4; j++) {
                int dd = c4 * 4 + j;
                float qv = qe[j];
                if (fabsf(qv) < REPAIR_TH)
                    qv = exact_dot768(xrow, qkv_w + (size_t)(h * HDIM + dd) * GK);
                float kv = ke[j];
                if (fabsf(kv) < REPAIR_TH)
                    kv = exact_dot768(xrow, qkv_w + (size_t)(CDIM + h * HDIM + dd) * GK);
                if (qv > 0.f) qm |= 1ull << dd;
                if (kv > 0.f) km |= 1ull << dd;
            }
        }
        g_qb[bh * NTOK + n] = qm;
        g_kb[bh * NTOK + n] = km;
    }

    const float SV = 2.0f / 127.0f;
    for (int i = threadIdx.x; i < HDIM * NW; i += 256) {
        int dd = i / NW, w = i % NW;
        unsigned int word = 0;
        #pragma unroll
        for (int j = 0; j < 4; j++) {
            int m = 4 * w + j;
            int vi = 0;
            if (m < NTOK) {
                float v = vb_[(size_t)m * CK + dd];
                v = fminf(fmaxf(v, -2.f), 2.f);
                float r = rintf(v / SV);
                r = fminf(fmaxf(r, -127.f), 127.f);
                vi = (int)r;
            }
            word |= ((unsigned)vi & 0xFFu) << (8 * j);
        }
        g_vT[(size_t)bh * HDIM * NW + i] = word;
    }
}

// ---------------- fused binary attention ----------------
__global__ __launch_bounds__(256) void attn_kernel(
    const float* __restrict__ rel_table, const int* __restrict__ rel_index,
    float* __restrict__ att)
{
    __shared__ unsigned long long qb_s[NTOK], kb_s[NTOK];
    __shared__ float rel_s[NRD];
    __shared__ unsigned int v_s[HDIM * NW];
    __shared__ __align__(4) unsigned char p_bytes[8 * 224];

    const int bh = blockIdx.x;
    const int b = bh / HEADS, h = bh % HEADS;
    const int tid = threadIdx.x;

    for (int i = tid; i < NTOK; i += 256) {
        qb_s[i] = g_qb[bh * NTOK + i];
        kb_s[i] = g_kb[bh * NTOK + i];
    }
    for (int i = tid; i < NRD; i += 256) rel_s[i] = rel_table[i * HEADS + h];
    for (int i = tid; i < HDIM * NW; i += 256) v_s[i] = g_vT[(size_t)bh * HDIM * NW + i];
    __syncthreads();

    const float sqk = g_sq[bh] * g_sk[bh];
    const float SP  = 1.0f / 255.0f;
    const float OSC = (1.0f / 255.0f) * (2.0f / 127.0f);
    const int warp = tid >> 5, lane = tid & 31;

    for (int n = warp; n < NTOK; n += 8) {
        const unsigned long long qm = qb_s[n];
        const int* ridx = rel_index + n * NTOK;

        float logit[7];
        float mx = -3.0e38f;
        #pragma unroll
        for (int t = 0; t < 7; t++) {
            int m = lane + (t << 5);
            float lg = -3.0e38f;
            if (m < NTOK) {
                int dot = 64 - 2 * __popcll(qm ^ kb_s[m]);
                lg = (sqk * (float)dot) * 0.125f + rel_s[ridx[m]];
            }
            logit[t] = lg;
            mx = fmaxf(mx, lg);
        }
        #pragma unroll
        for (int o = 16; o; o >>= 1) mx = fmaxf(mx, __shfl_xor_sync(0xffffffffu, mx, o));

        float e[7], sum = 0.f;
        #pragma unroll
        for (int t = 0; t < 7; t++) {
            int m = lane + (t << 5);
            e[t] = (m < NTOK) ? expf(logit[t] - mx) : 0.f;
            sum += e[t];
        }
        #pragma unroll
        for (int o = 16; o; o >>= 1) sum += __shfl_xor_sync(0xffffffffu, sum, o);

        unsigned char* pb = p_bytes + warp * 224;
        #pragma unroll
        for (int t = 0; t < 7; t++) {
            int m = lane + (t << 5);
            int pi = 0;
            if (m < NTOK) {
                float p = e[t] / sum;
                float r = rintf(p / SP);
                r = fminf(fmaxf(r, 0.f), 255.f);
                pi = (int)r;
            }
            pb[m] = (unsigned char)pi;
        }
        __syncwarp();

        const unsigned int* pw = (const unsigned int*)pb;
        const unsigned int* v0 = &v_s[lane * NW];
        const unsigned int* v1 = &v_s[(lane + 32) * NW];
        int acc0 = 0, acc1 = 0;
        #pragma unroll
        for (int w = 0; w < NW; w++) {
            unsigned int pword = pw[w];
            acc0 = dp4a_us(pword, v0[w], acc0);
            acc1 = dp4a_us(pword, v1[w], acc1);
        }

        float* orow = att + (size_t)(b * NTOK + n) * CDIM + h * HDIM;
        orow[lane]      = (float)acc0 * OSC;
        orow[lane + 32] = (float)acc1 * OSC;
        __syncwarp();
    }
}

// ---------------- launcher ----------------
extern "C" void kernel_launch(void* const* d_in, const int* in_sizes, int n_in,
                              void* d_out, int out_size)
{
    const float* x         = (const float*)d_in[0];
    const float* qkv_w     = (const float*)d_in[1];
    const float* proj_w    = (const float*)d_in[2];
    const float* proj_b    = (const float*)d_in[3];
    const float* rel_table = (const float*)d_in[4];
    const int*   rel_index = (const int*)d_in[5];
    float* out = (float*)d_out;

    float *qkv_ptr = nullptr, *att_ptr = nullptr;
    cudaGetSymbolAddress((void**)&qkv_ptr, g_qkv);
    cudaGetSymbolAddress((void**)&att_ptr, g_att);

    cudaFuncSetAttribute(gemm_f16c, cudaFuncAttributeMaxDynamicSharedMemorySize, GSMEM);

    const int GY = (MROWS + TBM - 1) / TBM;  // 99

    // 1) qkv = x @ qkv_w^T — single uniform P=3 launch (QK sign safety comes
    //    from the exact repair in pack_kernel; V P=3 validated in R11)
    dim3 g1(CK / TBN, GY);
    gemm_f16c<<<g1, 256, GSMEM>>>(x, qkv_w, nullptr, qkv_ptr, MROWS, CK);

    // 2) per-(b,h) scales for q,k
    scales_kernel<<<BHT * 2, 256>>>(qkv_ptr);

    // 3) sign-pack q,k (with exact fp32 repair near zero); int8 v
    pack_kernel<<<BHT, 256>>>(qkv_ptr, x, qkv_w);

    // 4) fused binary attention
    attn_kernel<<<BHT, 256>>>(rel_table, rel_index, att_ptr);

    // 5) out = att @ proj_w^T + proj_b: P=3 (no quantizer downstream)
    dim3 gp(CDIM / TBN, GY);
    gemm_f16c<<<gp, 256, GSMEM>>>(att_ptr, proj_w, proj_b, out, MROWS, CDIM);
}

// round 13
// speedup vs baseline: 1.0181x; 1.0181x over previous
#include <cuda_runtime.h>
#include <cuda_fp16.h>
#include <cstdint>

// ---------------- problem constants ----------------
#define BATCH 64
#define NTOK  197
#define HEADS 12
#define HDIM  64
#define CDIM  768
#define CK    2304
#define MROWS (BATCH*NTOK) // 12608
#define NRD   732
#define NW    50
#define BHT   (BATCH*HEADS)

// ---------------- device scratch (cudaMalloc is banned) -------------
__device__ float              g_qkv[(size_t)MROWS * CK];
__device__ float              g_att[(size_t)MROWS * CDIM];
__device__ float              g_sq[BHT];
__device__ float              g_sk[BHT];
__device__ unsigned long long g_qb[BHT * NTOK];
__device__ unsigned long long g_kb[BHT * NTOK];
__device__ unsigned int       g_vT[(size_t)BHT * HDIM * NW];

// ---------------- small helpers ----------------
__device__ __forceinline__ int dp4a_us(unsigned int a, unsigned int b, int c) {
    int d; asm("dp4a.u32.s32 %0, %1, %2, %3;" : "=r"(d) : "r"(a), "r"(b), "r"(c));
    return d;
}
__device__ __forceinline__ void mma_f16(float* c, const uint32_t* a, const uint32_t* b) {
    asm volatile(
        "mma.sync.aligned.m16n8k16.row.col.f32.f16.f16.f32 "
        "{%0,%1,%2,%3}, {%4,%5,%6,%7}, {%8,%9}, {%0,%1,%2,%3};"
        : "+f"(c[0]), "+f"(c[1]), "+f"(c[2]), "+f"(c[3])
        : "r"(a[0]), "r"(a[1]), "r"(a[2]), "r"(a[3]), "r"(b[0]), "r"(b[1]));
}
// NATURAL-scale fp16 2-way splits (R13): residuals stored at their own scale
// so all three products a0b0, a0b1, a1b0 share ONE scale (2^-5) and chain in
// a single mma fragment. Subnormal residuals are retained by HMMA with
// quantum 2^-24 (R9 evidence) — error contribution negligible.
//   A (x ~ O(1)):   x    = a0 + a1 + O(2^-24)      [a1 ~ 1.2e-4]
//   W (w ~ 0.02):   32*w = b0 + b1 + O(2^-24)      [b1 ~ 1.5e-4]
// x*w = 2^-5*(a0b0 + a0b1 + a1b0) + a1*b1 (~1.6e-8, dropped; QK repaired)
__device__ __forceinline__ void hsplitA(float x, uint16_t& s0, uint16_t& s1) {
    __half h0 = __float2half_rn(x);
    __half h1 = __float2half_rn(x - __half2float(h0));
    s0 = *reinterpret_cast<uint16_t*>(&h0);
    s1 = *reinterpret_cast<uint16_t*>(&h1);
}
__device__ __forceinline__ void hsplitB(float w, uint16_t& s0, uint16_t& s1) {
    float ws = w * 32.0f;
    __half h0 = __float2half_rn(ws);
    __half h1 = __float2half_rn(ws - __half2float(h0));
    s0 = *reinterpret_cast<uint16_t*>(&h0);
    s1 = *reinterpret_cast<uint16_t*>(&h1);
}

#define SC_HH 0.03125f                    // 2^-5

// ====== compensated-fp16 mma.sync GEMM, single-fragment fp32 drain ==========
// C[M,N] = A[M,768] @ W[N,768]^T (+bias), leading dim ldc.
// Per (mt,nt) tile per k-tile: 3 mmas (00, 01, 10) chained into ONE zero-init
// fragment (partials small -> weak mma C-path rounds small values), then a
// single exact-pow2 FFMA drain into fp32 registers. Long-range accumulation
// never touches the mma C-path (R8-validated mechanism, R13 de-overheaded).
#define GK      768
#define TBM     128
#define TBN     128
#define TBK     16
#define KT      (GK / TBK)          // 48
#define RPAD    12                  // u32 per smem row (8 data + 4 pad)
#define TILEU   (128 * RPAD)        // u32 per tile
#define GSMEM   (2 * 2 * 2 * TILEU * 4)   // 49,152 B

__global__ void __launch_bounds__(256, 1) gemm_f16c(
    const float* __restrict__ A, const float* __restrict__ W,
    const float* __restrict__ bias, float* __restrict__ C,
    int M, int ldc)
{
    extern __shared__ uint32_t smu[];
    auto tbase = [&](int buf, int mat, int t) -> uint32_t* {
        return smu + (size_t)(((buf * 2 + mat) * 2) + t) * TILEU;
    };

    const int tid  = threadIdx.x;
    const int wid  = tid >> 5;
    const int lane = tid & 31;
    const int gq   = lane >> 2;             // 0..7
    const int tq   = lane & 3;              // 0..3
    const int bm = blockIdx.y * TBM;
    const int bn = blockIdx.x * TBN;
    const int wm = (wid >> 2) * 64;
    const int wn = (wid & 3) * 32;

    // ---- producer mapping: 1 row x 8 k-floats per matrix per thread ----
    const int prow = tid >> 1;              // 0..127
    const int kseg = tid & 1;               // 0/1 -> k offset 0/8
    int arow = bm + prow; if (arow >= M) arow = M - 1;
    const float* gA = A + (size_t)arow * GK + kseg * 8;
    const float* gW = W + (size_t)(bn + prow) * GK + kseg * 8;
    const int off = prow * RPAD + kseg * 4; // u32 index (16B aligned)

    float4 stage[2][4];   // [set][A.lo4, A.hi4, W.lo4, W.hi4]; stage s -> set s&1

    auto ldg_stage = [&](int set, int kt) {
        const int kof = kt * TBK;
        stage[set][0] = *(const float4*)(gA + kof);
        stage[set][1] = *(const float4*)(gA + kof + 4);
        stage[set][2] = *(const float4*)(gW + kof);
        stage[set][3] = *(const float4*)(gW + kof + 4);
    };
    auto pack8 = [&](float4 v0, float4 v1, int buf, int mat) {
        float xs[8] = {v0.x, v0.y, v0.z, v0.w, v1.x, v1.y, v1.z, v1.w};
        uint16_t s0[8], s1[8];
        #pragma unroll
        for (int i = 0; i < 8; i++) {
            if (mat == 0) hsplitA(xs[i], s0[i], s1[i]);
            else          hsplitB(xs[i], s0[i], s1[i]);
        }
        uint4 t0, t1;
        t0.x = (uint32_t)s0[0] | ((uint32_t)s0[1] << 16);
        t0.y = (uint32_t)s0[2] | ((uint32_t)s0[3] << 16);
        t0.z = (uint32_t)s0[4] | ((uint32_t)s0[5] << 16);
        t0.w = (uint32_t)s0[6] | ((uint32_t)s0[7] << 16);
        t1.x = (uint32_t)s1[0] | ((uint32_t)s1[1] << 16);
        t1.y = (uint32_t)s1[2] | ((uint32_t)s1[3] << 16);
        t1.z = (uint32_t)s1[4] | ((uint32_t)s1[5] << 16);
        t1.w = (uint32_t)s1[6] | ((uint32_t)s1[7] << 16);
        *(uint4*)(tbase(buf, mat, 0) + off) = t0;
        *(uint4*)(tbase(buf, mat, 1) + off) = t1;
    };
    auto convert_store = [&](int set, int buf) {
        pack8(stage[set][0], stage[set][1], buf, 0);
        pack8(stage[set][2], stage[set][3], buf, 1);
    };

    float acc[4][4][4];
    #pragma unroll
    for (int i = 0; i < 4; i++)
        #pragma unroll
        for (int j = 0; j < 4; j++)
            #pragma unroll
            for (int r = 0; r < 4; r++) acc[i][j][r] = 0.f;

    // ---- prologue: stage0 -> set0 -> buf0; stage1 -> set1 ----
    ldg_stage(0, 0);
    convert_store(0, 0);
    ldg_stage(1, 1);
    __syncthreads();

    for (int kt = 0; kt < KT; ++kt) {
        const int cset = (kt + 1) & 1;                    // stage kt+1 lives in set (kt+1)&1
        if (kt + 1 < KT) convert_store(cset, (kt + 1) & 1);
        if (kt + 2 < KT) ldg_stage(cset ^ 1, kt + 2);     // stage kt+2 -> set (kt+2)&1

        const int buf = kt & 1;
        const uint32_t* at[2]; const uint32_t* bt[2];
        #pragma unroll
        for (int t = 0; t < 2; ++t) {
            at[t] = tbase(buf, 0, t) + (wm + gq) * RPAD;
            bt[t] = tbase(buf, 1, t) + (wn + gq) * RPAD;
        }

        // B fragments: 2 terms x 4 n-tiles
        uint32_t bf[2][4][2];
        #pragma unroll
        for (int t = 0; t < 2; ++t)
            #pragma unroll
            for (int nt = 0; nt < 4; ++nt) {
                const uint32_t* bp = bt[t] + nt * 8 * RPAD + tq;
                bf[t][nt][0] = bp[0];
                bf[t][nt][1] = bp[4];
            }
        #pragma unroll
        for (int mt = 0; mt < 4; ++mt) {
            uint32_t af[2][4];
            #pragma unroll
            for (int t = 0; t < 2; ++t) {
                const uint32_t* ap = at[t] + mt * 16 * RPAD + tq;
                af[t][0] = ap[0];
                af[t][1] = ap[8 * RPAD];
                af[t][2] = ap[4];
                af[t][3] = ap[8 * RPAD + 4];
            }
            #pragma unroll
            for (int nt = 0; nt < 4; ++nt) {
                // single zero-init fragment; all 3 products share scale 2^-5
                float d[4] = {0.f, 0.f, 0.f, 0.f};
                mma_f16(d, af[0], bf[0][nt]);             // a0 b0
                mma_f16(d, af[0], bf[1][nt]);             // a0 b1 (natural)
                mma_f16(d, af[1], bf[0][nt]);             // a1 b0 (natural)
                #pragma unroll
                for (int r = 0; r < 4; ++r)
                    acc[mt][nt][r] = fmaf(d[r], SC_HH, acc[mt][nt][r]);
            }
        }
        __syncthreads();
    }

    // ---- epilogue ----
    #pragma unroll
    for (int mt = 0; mt < 4; ++mt) {
        int r0 = bm + wm + mt * 16 + gq;
        int r1 = r0 + 8;
        #pragma unroll
        for (int nt = 0; nt < 4; ++nt) {
            int c = bn + wn + nt * 8 + tq * 2;
            float b0 = bias ? bias[c]     : 0.f;
            float b1 = bias ? bias[c + 1] : 0.f;
            if (r0 < M) {
                float2 v; v.x = acc[mt][nt][0] + b0; v.y = acc[mt][nt][1] + b1;
                *(float2*)(C + (size_t)r0 * ldc + c) = v;
            }
            if (r1 < M) {
                float2 v; v.x = acc[mt][nt][2] + b0; v.y = acc[mt][nt][3] + b1;
                *(float2*)(C + (size_t)r1 * ldc + c) = v;
            }
        }
    }
}

// ---------------- per-(b,h) |q| / |k| mean scales ----------------
__global__ __launch_bounds__(256) void scales_kernel(const float* __restrict__ qkv)
{
    __shared__ float red[256];
    const int which = blockIdx.x & 1;
    const int bh    = blockIdx.x >> 1;
    const int b = bh / HEADS, h = bh % HEADS;
    const float* base = qkv + (size_t)b * NTOK * CK + which * CDIM + h * HDIM;

    float s = 0.f;
    for (int i = threadIdx.x; i < NTOK * HDIM; i += 256) {
        int n = i >> 6, dd = i & 63;
        s += fabsf(base[(size_t)n * CK + dd]);
    }
    red[threadIdx.x] = s; __syncthreads();
    for (int o = 128; o; o >>= 1) {
        if (threadIdx.x < o) red[threadIdx.x] += red[threadIdx.x + o];
        __syncthreads();
    }
    if (threadIdx.x == 0) {
        float v = red[0] / 12608.0f;
        if (which) g_sk[bh] = v; else g_sq[bh] = v;
    }
}

// ---------------- pack: sign bits (with exact fp32 repair), int8 v ---------
// REPAIR: q/k elements with |value| < 1e-4 (GEMM error ~4e-7, so only these
// can sign-flip) are recomputed exactly in fp32 (4-way ILP dot).
#define REPAIR_TH 1e-4f
__device__ __forceinline__ float exact_dot768(const float* __restrict__ xr,
                                              const float* __restrict__ wr) {
    float s0 = 0.f, s1 = 0.f, s2 = 0.f, s3 = 0.f;
    #pragma unroll 4
    for (int i = 0; i < GK; i += 4) {
        s0 = fmaf(xr[i+0], wr[i+0], s0);
        s1 = fmaf(xr[i+1], wr[i+1], s1);
        s2 = fmaf(xr[i+2], wr[i+2], s2);
        s3 = fmaf(xr[i+3], wr[i+3], s3);
    }
    return (s0 + s1) + (s2 + s3);
}

__global__ __launch_bounds__(256) void pack_kernel(
    const float* __restrict__ qkv,
    const float* __restrict__ x, const float* __restrict__ qkv_w)
{
    const int bh = blockIdx.x;
    const int b = bh / HEADS, h = bh % HEADS;
    const size_t rowbase = (size_t)b * NTOK * CK + h * HDIM;
    const float* qb_ = qkv + rowbase;
    const float* kb_ = qkv + rowbase + CDIM;
    const float* vb_ = qkv + rowbase + 2 * CDIM;

    for (int n = threadIdx.x; n < NTOK; n += 256) {
        const float* qr = qb_ + (size_t)n * CK;
        const float* kr = kb_ + (size_t)n * CK;
        const float* xrow = x + (size_t)(b * NTOK + n) * GK;
        unsigned long long qm = 0ull, km = 0ull;
        #pragma unroll
        for (int c4 = 0; c4 < 16; c4++) {
            float qe[4], ke[4];
            *(float4*)qe = *(const float4*)(qr + c4 * 4);
            *(float4*)ke = *(const float4*)(kr + c4 * 4);
            #pragma unroll
            for (int j = 0; j < 4; j++) {
                int dd = c4 * 4 + j;
                float qv = qe[j];
                if (fabsf(qv) < REPAIR_TH)
                    qv = exact_dot768(xrow, qkv_w + (size_t)(h * HDIM + dd) * GK);
                float kv = ke[j];
                if (fabsf(kv) < REPAIR_TH)
                    kv = exact_dot768(xrow, qkv_w + (size_t)(CDIM + h * HDIM + dd) * GK);
                if (qv > 0.f) qm |= 1ull << dd;
                if (kv > 0.f) km |= 1ull << dd;
            }
        }
        g_qb[bh * NTOK + n] = qm;
        g_kb[bh * NTOK + n] = km;
    }

    const float SV = 2.0f / 127.0f;
    for (int i = threadIdx.x; i < HDIM * NW; i += 256) {
        int dd = i / NW, w = i % NW;
        unsigned int word = 0;
        #pragma unroll
        for (int j = 0; j < 4; j++) {
            int m = 4 * w + j;
            int vi = 0;
            if (m < NTOK) {
                float v = vb_[(size_t)m * CK + dd];
                v = fminf(fmaxf(v, -2.f), 2.f);
                float r = rintf(v / SV);
                r = fminf(fmaxf(r, -127.f), 127.f);
                vi = (int)r;
            }
            word |= ((unsigned)vi & 0xFFu) << (8 * j);
        }
        g_vT[(size_t)bh * HDIM * NW + i] = word;
    }
}

// ---------------- fused binary attention ----------------
__global__ __launch_bounds__(256) void attn_kernel(
    const float* __restrict__ rel_table, const int* __restrict__ rel_index,
    float* __restrict__ att)
{
    __shared__ unsigned long long qb_s[NTOK], kb_s[NTOK];
    __shared__ float rel_s[NRD];
    __shared__ unsigned int v_s[HDIM * NW];
    __shared__ __align__(4) unsigned char p_bytes[8 * 224];

    const int bh = blockIdx.x;
    const int b = bh / HEADS, h = bh % HEADS;
    const int tid = threadIdx.x;

    for (int i = tid; i < NTOK; i += 256) {
        qb_s[i] = g_qb[bh * NTOK + i];
        kb_s[i] = g_kb[bh * NTOK + i];
    }
    for (int i = tid; i < NRD; i += 256) rel_s[i] = rel_table[i * HEADS + h];
    for (int i = tid; i < HDIM * NW; i += 256) v_s[i] = g_vT[(size_t)bh * HDIM * NW + i];
    __syncthreads();

    const float sqk = g_sq[bh] * g_sk[bh];
    const float SP  = 1.0f / 255.0f;
    const float OSC = (1.0f / 255.0f) * (2.0f / 127.0f);
    const int warp = tid >> 5, lane = tid & 31;

    for (int n = warp; n < NTOK; n += 8) {
        const unsigned long long qm = qb_s[n];
        const int* ridx = rel_index + n * NTOK;

        float logit[7];
        float mx = -3.0e38f;
        #pragma unroll
        for (int t = 0; t < 7; t++) {
            int m = lane + (t << 5);
            float lg = -3.0e38f;
            if (m < NTOK) {
                int dot = 64 - 2 * __popcll(qm ^ kb_s[m]);
                lg = (sqk * (float)dot) * 0.125f + rel_s[ridx[m]];
            }
            logit[t] = lg;
            mx = fmaxf(mx, lg);
        }
        #pragma unroll
        for (int o = 16; o; o >>= 1) mx = fmaxf(mx, __shfl_xor_sync(0xffffffffu, mx, o));

        float e[7], sum = 0.f;
        #pragma unroll
        for (int t = 0; t < 7; t++) {
            int m = lane + (t << 5);
            e[t] = (m < NTOK) ? expf(logit[t] - mx) : 0.f;
            sum += e[t];
        }
        #pragma unroll
        for (int o = 16; o; o >>= 1) sum += __shfl_xor_sync(0xffffffffu, sum, o);

        unsigned char* pb = p_bytes + warp * 224;
        #pragma unroll
        for (int t = 0; t < 7; t++) {
            int m = lane + (t << 5);
            int pi = 0;
            if (m < NTOK) {
                float p = e[t] / sum;
                float r = rintf(p / SP);
                r = fminf(fmaxf(r, 0.f), 255.f);
                pi = (int)r;
            }
            pb[m] = (unsigned char)pi;
        }
        __syncwarp();

        const unsigned int* pw = (const unsigned int*)pb;
        const unsigned int* v0 = &v_s[lane * NW];
        const unsigned int* v1 = &v_s[(lane + 32) * NW];
        int acc0 = 0, acc1 = 0;
        #pragma unroll
        for (int w = 0; w < NW; w++) {
            unsigned int pword = pw[w];
            acc0 = dp4a_us(pword, v0[w], acc0);
            acc1 = dp4a_us(pword, v1[w], acc1);
        }

        float* orow = att + (size_t)(b * NTOK + n) * CDIM + h * HDIM;
        orow[lane]      = (float)acc0 * OSC;
        orow[lane + 32] = (float)acc1 * OSC;
        __syncwarp();
    }
}

// ---------------- launcher ----------------
extern "C" void kernel_launch(void* const* d_in, const int* in_sizes, int n_in,
                              void* d_out, int out_size)
{
    const float* x         = (const float*)d_in[0];
    const float* qkv_w     = (const float*)d_in[1];
    const float* proj_w    = (const float*)d_in[2];
    const float* proj_b    = (const float*)d_in[3];
    const float* rel_table = (const float*)d_in[4];
    const int*   rel_index = (const int*)d_in[5];
    float* out = (float*)d_out;

    float *qkv_ptr = nullptr, *att_ptr = nullptr;
    cudaGetSymbolAddress((void**)&qkv_ptr, g_qkv);
    cudaGetSymbolAddress((void**)&att_ptr, g_att);

    cudaFuncSetAttribute(gemm_f16c, cudaFuncAttributeMaxDynamicSharedMemorySize, GSMEM);

    const int GY = (MROWS + TBM - 1) / TBM;  // 99

    // 1) qkv = x @ qkv_w^T — single-fragment P=3 (QK sign safety via repair)
    dim3 g1(CK / TBN, GY);
    gemm_f16c<<<g1, 256, GSMEM>>>(x, qkv_w, nullptr, qkv_ptr, MROWS, CK);

    // 2) per-(b,h) scales for q,k
    scales_kernel<<<BHT * 2, 256>>>(qkv_ptr);

    // 3) sign-pack q,k (with exact fp32 repair near zero); int8 v
    pack_kernel<<<BHT, 256>>>(qkv_ptr, x, qkv_w);

    // 4) fused binary attention
    attn_kernel<<<BHT, 256>>>(rel_table, rel_index, att_ptr);

    // 5) out = att @ proj_w^T + proj_b
    dim3 gp(CDIM / TBN, GY);
    gemm_f16c<<<gp, 256, GSMEM>>>(att_ptr, proj_w, proj_b, out, MROWS, CDIM);
}

// round 14
// speedup vs baseline: 1.4504x; 1.4245x over previous
#include <cuda_runtime.h>
#include <cuda_fp16.h>
#include <cstdint>

// ---------------- problem constants ----------------
#define BATCH 64
#define NTOK  197
#define HEADS 12
#define HDIM  64
#define CDIM  768
#define CK    2304
#define MROWS (BATCH*NTOK) // 12608
#define NRD   732
#define NW    50
#define BHT   (BATCH*HEADS)
#define GK    768

// ---------------- device scratch (cudaMalloc is banned) -------------
__device__ float              g_qkv[(size_t)MROWS * CK];
__device__ float              g_sq[BHT];
__device__ float              g_sk[BHT];
__device__ unsigned long long g_qb[BHT * NTOK];
__device__ unsigned long long g_kb[BHT * NTOK];
__device__ unsigned int       g_vT[(size_t)BHT * HDIM * NW];
// pre-split fp16 planes
__device__ __half             g_x0[(size_t)MROWS * GK];
__device__ __half             g_x1[(size_t)MROWS * GK];
__device__ __half             g_w0[(size_t)CK * GK];
__device__ __half             g_w1[(size_t)CK * GK];
__device__ __half             g_p0[(size_t)CDIM * GK];
__device__ __half             g_p1[(size_t)CDIM * GK];
__device__ __half             g_a0[(size_t)MROWS * CDIM];
__device__ __half             g_a1[(size_t)MROWS * CDIM];

// ---------------- small helpers ----------------
__device__ __forceinline__ int dp4a_us(unsigned int a, unsigned int b, int c) {
    int d; asm("dp4a.u32.s32 %0, %1, %2, %3;" : "=r"(d) : "r"(a), "r"(b), "r"(c));
    return d;
}
__device__ __forceinline__ void mma_f16(float* c, const uint32_t* a, const uint32_t* b) {
    asm volatile(
        "mma.sync.aligned.m16n8k16.row.col.f32.f16.f16.f32 "
        "{%0,%1,%2,%3}, {%4,%5,%6,%7}, {%8,%9}, {%0,%1,%2,%3};"
        : "+f"(c[0]), "+f"(c[1]), "+f"(c[2]), "+f"(c[3])
        : "r"(a[0]), "r"(a[1]), "r"(a[2]), "r"(a[3]), "r"(b[0]), "r"(b[1]));
}
__device__ __forceinline__ uint32_t smem_u32(const void* p) {
    uint32_t a;
    asm("{ .reg .u64 t; cvta.to.shared.u64 t, %1; cvt.u32.u64 %0, t; }" : "=r"(a) : "l"(p));
    return a;
}
__device__ __forceinline__ void cpasync16(uint32_t s, const void* g) {
    asm volatile("cp.async.cg.shared.global [%0], [%1], 16;" :: "r"(s), "l"(g));
}
// NATURAL-scale fp16 2-way splits (R13-validated):
//   A (x ~ O(1)):   x    = a0 + a1           [a1 subnormal-safe, quantum 2^-24]
//   W (w ~ 0.02):   32*w = b0 + b1
// x*w = 2^-5*(a0b0 + a0b1 + a1b0) + (a1b1 dropped; QK signs repaired exactly)
__device__ __forceinline__ void hsplitA(float x, __half& s0, __half& s1) {
    s0 = __float2half_rn(x);
    s1 = __float2half_rn(x - __half2float(s0));
}
__device__ __forceinline__ void hsplitB(float w, __half& s0, __half& s1) {
    float ws = w * 32.0f;
    s0 = __float2half_rn(ws);
    s1 = __float2half_rn(ws - __half2float(s0));
}
#define SC_HH 0.03125f                    // 2^-5

// ---------------- split kernels (run once per buffer) ----------------
__global__ __launch_bounds__(256) void split_kernel(
    const float* __restrict__ src, __half* __restrict__ d0, __half* __restrict__ d1,
    int n4, int isB)
{
    int i = blockIdx.x * 256 + threadIdx.x;
    if (i >= n4) return;
    float4 v = *(const float4*)(src + (size_t)i * 4);
    __half h0[4], h1[4];
    if (isB) {
        hsplitB(v.x, h0[0], h1[0]); hsplitB(v.y, h0[1], h1[1]);
        hsplitB(v.z, h0[2], h1[2]); hsplitB(v.w, h0[3], h1[3]);
    } else {
        hsplitA(v.x, h0[0], h1[0]); hsplitA(v.y, h0[1], h1[1]);
        hsplitA(v.z, h0[2], h1[2]); hsplitA(v.w, h0[3], h1[3]);
    }
    *(uint2*)(d0 + (size_t)i * 4) = *(uint2*)h0;
    *(uint2*)(d1 + (size_t)i * 4) = *(uint2*)h1;
}

// ======= cp.async fp16 split-GEMM, single-fragment fp32 drain (R14) =========
// C[M,N] = (A0+A1)[M,768] @ ((B0+B1))[N,768]^T * 2^-5 (+bias), ld = ldc.
// 3-stage cp.async pipeline, TBK=32; MMA arithmetic per 16-k step identical
// to R13 (3 products -> zero-init fragment -> exact-pow2 FFMA drain).
#define TBM   128
#define TBN   128
#define TBK   32
#define STG   3
#define ROWH  40                    // halfs per smem row (32 data + 8 pad)
#define TILEH (128 * ROWH)          // 5120 halfs per tile
#define STAGEH (4 * TILEH)          // A0,A1,B0,B1
#define GSMEM (STG * STAGEH * 2)    // 122,880 B

__global__ void __launch_bounds__(256, 1) gemm_h(
    const __half* __restrict__ A0, const __half* __restrict__ A1,
    const __half* __restrict__ B0, const __half* __restrict__ B1,
    const float* __restrict__ bias, float* __restrict__ C,
    int M, int ldc)
{
    extern __shared__ __half smh[];
    const uint32_t sbyte = smem_u32(smh);

    const int tid  = threadIdx.x;
    const int wid  = tid >> 5;
    const int lane = tid & 31;
    const int gq   = lane >> 2;
    const int tq   = lane & 3;
    const int bm = blockIdx.y * TBM;
    const int bn = blockIdx.x * TBN;
    const int wm = (wid >> 2) * 64;
    const int wn = (wid & 3) * 32;
    const int KT = GK / TBK;        // 24

    // per-thread cp.async mapping: 2 chunks of 16B per tile, 4 tiles
    const int c0 = tid * 2;
    const int row0 = c0 >> 2, col0 = c0 & 3;
    const int row1 = (c0 + 1) >> 2, col1 = (c0 + 1) & 3;
    int ar0 = bm + row0; if (ar0 >= M) ar0 = M - 1;
    int ar1 = bm + row1; if (ar1 >= M) ar1 = M - 1;

    const __half* gsrc[4] = {A0, A1, B0, B1};

    auto issue_stage = [&](int kt) {
        const int k0 = kt * TBK;
        const uint32_t sb = sbyte + (uint32_t)(kt % STG) * STAGEH * 2;
        #pragma unroll
        for (int t = 0; t < 4; ++t) {
            int r0 = (t < 2) ? ar0 : (bn + row0);
            int r1 = (t < 2) ? ar1 : (bn + row1);
            cpasync16(sb + (uint32_t)(t * TILEH + row0 * ROWH + col0 * 8) * 2,
                      gsrc[t] + (size_t)r0 * GK + k0 + col0 * 8);
            cpasync16(sb + (uint32_t)(t * TILEH + row1 * ROWH + col1 * 8) * 2,
                      gsrc[t] + (size_t)r1 * GK + k0 + col1 * 8);
        }
    };

    float acc[4][4][4];
    #pragma unroll
    for (int i = 0; i < 4; i++)
        #pragma unroll
        for (int j = 0; j < 4; j++)
            #pragma unroll
            for (int r = 0; r < 4; r++) acc[i][j][r] = 0.f;

    // prologue: stages 0,1 in flight
    issue_stage(0);
    asm volatile("cp.async.commit_group;" ::: "memory");
    issue_stage(1);
    asm volatile("cp.async.commit_group;" ::: "memory");

    for (int kt = 0; kt < KT; ++kt) {
        asm volatile("cp.async.wait_group %0;" :: "n"(1) : "memory");
        __syncthreads();
        if (kt + 2 < KT) issue_stage(kt + 2);
        asm volatile("cp.async.commit_group;" ::: "memory");

        const uint32_t* sp = (const uint32_t*)smh + (size_t)(kt % STG) * STAGEH / 2;
        const uint32_t* at[2] = { sp + 0 * (TILEH/2) + (wm + gq) * (ROWH/2),
                                  sp + 1 * (TILEH/2) + (wm + gq) * (ROWH/2) };
        const uint32_t* bt[2] = { sp + 2 * (TILEH/2) + (wn + gq) * (ROWH/2),
                                  sp + 3 * (TILEH/2) + (wn + gq) * (ROWH/2) };

        #pragma unroll
        for (int kk8 = 0; kk8 < TBK/2; kk8 += 8) {     // two 16-k steps
            uint32_t bf[2][4][2];
            #pragma unroll
            for (int t = 0; t < 2; ++t)
                #pragma unroll
                for (int nt = 0; nt < 4; ++nt) {
                    const uint32_t* bp = bt[t] + nt * 8 * (ROWH/2) + kk8 + tq;
                    bf[t][nt][0] = bp[0];
                    bf[t][nt][1] = bp[4];
                }
            #pragma unroll
            for (int mt = 0; mt < 4; ++mt) {
                uint32_t af[2][4];
                #pragma unroll
                for (int t = 0; t < 2; ++t) {
                    const uint32_t* ap = at[t] + mt * 16 * (ROWH/2) + kk8 + tq;
                    af[t][0] = ap[0];
                    af[t][1] = ap[8 * (ROWH/2)];
                    af[t][2] = ap[4];
                    af[t][3] = ap[8 * (ROWH/2) + 4];
                }
                #pragma unroll
                for (int nt = 0; nt < 4; ++nt) {
                    float d[4] = {0.f, 0.f, 0.f, 0.f};
                    mma_f16(d, af[0], bf[0][nt]);      // a0 b0
                    mma_f16(d, af[0], bf[1][nt]);      // a0 b1
                    mma_f16(d, af[1], bf[0][nt]);      // a1 b0
                    #pragma unroll
                    for (int r = 0; r < 4; ++r)
                        acc[mt][nt][r] = fmaf(d[r], SC_HH, acc[mt][nt][r]);
                }
            }
        }
        __syncthreads();
    }

    // ---- epilogue ----
    #pragma unroll
    for (int mt = 0; mt < 4; ++mt) {
        int r0 = bm + wm + mt * 16 + gq;
        int r1 = r0 + 8;
        #pragma unroll
        for (int nt = 0; nt < 4; ++nt) {
            int c = bn + wn + nt * 8 + tq * 2;
            float b0 = bias ? bias[c]     : 0.f;
            float b1 = bias ? bias[c + 1] : 0.f;
            if (r0 < M) {
                float2 v; v.x = acc[mt][nt][0] + b0; v.y = acc[mt][nt][1] + b1;
                *(float2*)(C + (size_t)r0 * ldc + c) = v;
            }
            if (r1 < M) {
                float2 v; v.x = acc[mt][nt][2] + b0; v.y = acc[mt][nt][3] + b1;
                *(float2*)(C + (size_t)r1 * ldc + c) = v;
            }
        }
    }
}

// ---------------- per-(b,h) |q| / |k| mean scales ----------------
__global__ __launch_bounds__(256) void scales_kernel(const float* __restrict__ qkv)
{
    __shared__ float red[256];
    const int which = blockIdx.x & 1;
    const int bh    = blockIdx.x >> 1;
    const int b = bh / HEADS, h = bh % HEADS;
    const float* base = qkv + (size_t)b * NTOK * CK + which * CDIM + h * HDIM;

    float s = 0.f;
    for (int i = threadIdx.x; i < NTOK * HDIM; i += 256) {
        int n = i >> 6, dd = i & 63;
        s += fabsf(base[(size_t)n * CK + dd]);
    }
    red[threadIdx.x] = s; __syncthreads();
    for (int o = 128; o; o >>= 1) {
        if (threadIdx.x < o) red[threadIdx.x] += red[threadIdx.x + o];
        __syncthreads();
    }
    if (threadIdx.x == 0) {
        float v = red[0] / 12608.0f;
        if (which) g_sk[bh] = v; else g_sq[bh] = v;
    }
}

// ---------------- pack: sign bits (with exact fp32 repair), int8 v ---------
#define REPAIR_TH 1e-4f
__device__ __forceinline__ float exact_dot768(const float* __restrict__ xr,
                                              const float* __restrict__ wr) {
    float s0 = 0.f, s1 = 0.f, s2 = 0.f, s3 = 0.f;
    #pragma unroll 4
    for (int i = 0; i < GK; i += 4) {
        s0 = fmaf(xr[i+0], wr[i+0], s0);
        s1 = fmaf(xr[i+1], wr[i+1], s1);
        s2 = fmaf(xr[i+2], wr[i+2], s2);
        s3 = fmaf(xr[i+3], wr[i+3], s3);
    }
    return (s0 + s1) + (s2 + s3);
}

__global__ __launch_bounds__(256) void pack_kernel(
    const float* __restrict__ qkv,
    const float* __restrict__ x, const float* __restrict__ qkv_w)
{
    const int bh = blockIdx.x;
    const int b = bh / HEADS, h = bh % HEADS;
    const size_t rowbase = (size_t)b * NTOK * CK + h * HDIM;
    const float* qb_ = qkv + rowbase;
    const float* kb_ = qkv + rowbase + CDIM;
    const float* vb_ = qkv + rowbase + 2 * CDIM;

    for (int n = threadIdx.x; n < NTOK; n += 256) {
        const float* qr = qb_ + (size_t)n * CK;
        const float* kr = kb_ + (size_t)n * CK;
        const float* xrow = x + (size_t)(b * NTOK + n) * GK;
        unsigned long long qm = 0ull, km = 0ull;
        #pragma unroll
        for (int c4 = 0; c4 < 16; c4++) {
            float qe[4], ke[4];
            *(float4*)qe = *(const float4*)(qr + c4 * 4);
            *(float4*)ke = *(const float4*)(kr + c4 * 4);
            #pragma unroll
            for (int j = 0; j < 4; j++) {
                int dd = c4 * 4 + j;
                float qv = qe[j];
                if (fabsf(qv) < REPAIR_TH)
                    qv = exact_dot768(xrow, qkv_w + (size_t)(h * HDIM + dd) * GK);
                float kv = ke[j];
                if (fabsf(kv) < REPAIR_TH)
                    kv = exact_dot768(xrow, qkv_w + (size_t)(CDIM + h * HDIM + dd) * GK);
                if (qv > 0.f) qm |= 1ull << dd;
                if (kv > 0.f) km |= 1ull << dd;
            }
        }
        g_qb[bh * NTOK + n] = qm;
        g_kb[bh * NTOK + n] = km;
    }

    const float SV = 2.0f / 127.0f;
    for (int i = threadIdx.x; i < HDIM * NW; i += 256) {
        int dd = i / NW, w = i % NW;
        unsigned int word = 0;
        #pragma unroll
        for (int j = 0; j < 4; j++) {
            int m = 4 * w + j;
            int vi = 0;
            if (m < NTOK) {
                float v = vb_[(size_t)m * CK + dd];
                v = fminf(fmaxf(v, -2.f), 2.f);
                float r = rintf(v / SV);
                r = fminf(fmaxf(r, -127.f), 127.f);
                vi = (int)r;
            }
            word |= ((unsigned)vi & 0xFFu) << (8 * j);
        }
        g_vT[(size_t)bh * HDIM * NW + i] = word;
    }
}

// ---------------- fused binary attention (writes pre-split fp16 att) -------
__global__ __launch_bounds__(256) void attn_kernel(
    const float* __restrict__ rel_table, const int* __restrict__ rel_index)
{
    __shared__ unsigned long long qb_s[NTOK], kb_s[NTOK];
    __shared__ float rel_s[NRD];
    __shared__ unsigned int v_s[HDIM * NW];
    __shared__ __align__(4) unsigned char p_bytes[8 * 224];

    const int bh = blockIdx.x;
    const int b = bh / HEADS, h = bh % HEADS;
    const int tid = threadIdx.x;

    for (int i = tid; i < NTOK; i += 256) {
        qb_s[i] = g_qb[bh * NTOK + i];
        kb_s[i] = g_kb[bh * NTOK + i];
    }
    for (int i = tid; i < NRD; i += 256) rel_s[i] = rel_table[i * HEADS + h];
    for (int i = tid; i < HDIM * NW; i += 256) v_s[i] = g_vT[(size_t)bh * HDIM * NW + i];
    __syncthreads();

    const float sqk = g_sq[bh] * g_sk[bh];
    const float SP  = 1.0f / 255.0f;
    const float OSC = (1.0f / 255.0f) * (2.0f / 127.0f);
    const int warp = tid >> 5, lane = tid & 31;

    for (int n = warp; n < NTOK; n += 8) {
        const unsigned long long qm = qb_s[n];
        const int* ridx = rel_index + n * NTOK;

        float logit[7];
        float mx = -3.0e38f;
        #pragma unroll
        for (int t = 0; t < 7; t++) {
            int m = lane + (t << 5);
            float lg = -3.0e38f;
            if (m < NTOK) {
                int dot = 64 - 2 * __popcll(qm ^ kb_s[m]);
                lg = (sqk * (float)dot) * 0.125f + rel_s[ridx[m]];
            }
            logit[t] = lg;
            mx = fmaxf(mx, lg);
        }
        #pragma unroll
        for (int o = 16; o; o >>= 1) mx = fmaxf(mx, __shfl_xor_sync(0xffffffffu, mx, o));

        float e[7], sum = 0.f;
        #pragma unroll
        for (int t = 0; t < 7; t++) {
            int m = lane + (t << 5);
            e[t] = (m < NTOK) ? expf(logit[t] - mx) : 0.f;
            sum += e[t];
        }
        #pragma unroll
        for (int o = 16; o; o >>= 1) sum += __shfl_xor_sync(0xffffffffu, sum, o);

        unsigned char* pb = p_bytes + warp * 224;
        #pragma unroll
        for (int t = 0; t < 7; t++) {
            int m = lane + (t << 5);
            int pi = 0;
            if (m < NTOK) {
                float p = e[t] / sum;
                float r = rintf(p / SP);
                r = fminf(fmaxf(r, 0.f), 255.f);
                pi = (int)r;
            }
            pb[m] = (unsigned char)pi;
        }
        __syncwarp();

        const unsigned int* pw = (const unsigned int*)pb;
        const unsigned int* v0 = &v_s[lane * NW];
        const unsigned int* v1 = &v_s[(lane + 32) * NW];
        int acc0 = 0, acc1 = 0;
        #pragma unroll
        for (int w = 0; w < NW; w++) {
            unsigned int pword = pw[w];
            acc0 = dp4a_us(pword, v0[w], acc0);
            acc1 = dp4a_us(pword, v1[w], acc1);
        }

        // write pre-split fp16 att planes (same hsplitA arithmetic)
        size_t obase = (size_t)(b * NTOK + n) * CDIM + h * HDIM;
        float va = (float)acc0 * OSC;
        float vb = (float)acc1 * OSC;
        __half a0, a1;
        hsplitA(va, a0, a1);
        g_a0[obase + lane] = a0;
        g_a1[obase + lane] = a1;
        hsplitA(vb, a0, a1);
        g_a0[obase + lane + 32] = a0;
        g_a1[obase + lane + 32] = a1;
        __syncwarp();
    }
}

// ---------------- launcher ----------------
extern "C" void kernel_launch(void* const* d_in, const int* in_sizes, int n_in,
                              void* d_out, int out_size)
{
    const float* x         = (const float*)d_in[0];
    const float* qkv_w     = (const float*)d_in[1];
    const float* proj_w    = (const float*)d_in[2];
    const float* proj_b    = (const float*)d_in[3];
    const float* rel_table = (const float*)d_in[4];
    const int*   rel_index = (const int*)d_in[5];
    float* out = (float*)d_out;

    float *qkv_ptr = nullptr;
    cudaGetSymbolAddress((void**)&qkv_ptr, g_qkv);
    __half *x0, *x1, *w0, *w1, *p0, *p1, *a0, *a1;
    cudaGetSymbolAddress((void**)&x0, g_x0);
    cudaGetSymbolAddress((void**)&x1, g_x1);
    cudaGetSymbolAddress((void**)&w0, g_w0);
    cudaGetSymbolAddress((void**)&w1, g_w1);
    cudaGetSymbolAddress((void**)&p0, g_p0);
    cudaGetSymbolAddress((void**)&p1, g_p1);
    cudaGetSymbolAddress((void**)&a0, g_a0);
    cudaGetSymbolAddress((void**)&a1, g_a1);

    cudaFuncSetAttribute(gemm_h, cudaFuncAttributeMaxDynamicSharedMemorySize, GSMEM);

    // 0) pre-split inputs to fp16 planes
    {
        int n4 = MROWS * GK / 4;
        split_kernel<<<(n4 + 255) / 256, 256>>>(x, x0, x1, n4, 0);
        n4 = CK * GK / 4;
        split_kernel<<<(n4 + 255) / 256, 256>>>(qkv_w, w0, w1, n4, 1);
        n4 = CDIM * GK / 4;
        split_kernel<<<(n4 + 255) / 256, 256>>>(proj_w, p0, p1, n4, 1);
    }

    const int GY = (MROWS + TBM - 1) / TBM;  // 99

    // 1) qkv = x @ qkv_w^T  (cp.async fp16 split-GEMM)
    dim3 g1(CK / TBN, GY);
    gemm_h<<<g1, 256, GSMEM>>>(x0, x1, w0, w1, nullptr, qkv_ptr, MROWS, CK);

    // 2) per-(b,h) scales for q,k
    scales_kernel<<<BHT * 2, 256>>>(qkv_ptr);

    // 3) sign-pack q,k (with exact fp32 repair near zero); int8 v
    pack_kernel<<<BHT, 256>>>(qkv_ptr, x, qkv_w);

    // 4) fused binary attention -> pre-split fp16 att planes
    attn_kernel<<<BHT, 256>>>(rel_table, rel_index);

    // 5) out = att @ proj_w^T + proj_b
    dim3 gp(CDIM / TBN, GY);
    gemm_h<<<gp, 256, GSMEM>>>(a0, a1, p0, p1, proj_b, out, MROWS, CDIM);
}

// round 15
// speedup vs baseline: 1.5399x; 1.0618x over previous
#include <cuda_runtime.h>
#include <cuda_fp16.h>
#include <cstdint>

// ---------------- problem constants ----------------
#define BATCH 64
#define NTOK  197
#define HEADS 12
#define HDIM  64
#define CDIM  768
#define CK    2304
#define MROWS (BATCH*NTOK) // 12608
#define NRD   732
#define NW    50
#define BHT   (BATCH*HEADS)
#define GK    768

// ---------------- device scratch (cudaMalloc is banned) -------------
__device__ float              g_qkv[(size_t)MROWS * CK];
__device__ float              g_sq[BHT];
__device__ float              g_sk[BHT];
__device__ unsigned long long g_qb[BHT * NTOK];
__device__ unsigned long long g_kb[BHT * NTOK];
__device__ unsigned int       g_vT[(size_t)BHT * HDIM * NW];
// pre-split fp16 planes
__device__ __half             g_x0[(size_t)MROWS * GK];
__device__ __half             g_x1[(size_t)MROWS * GK];
__device__ __half             g_w0[(size_t)CK * GK];
__device__ __half             g_w1[(size_t)CK * GK];
__device__ __half             g_p0[(size_t)CDIM * GK];
__device__ __half             g_p1[(size_t)CDIM * GK];
__device__ __half             g_a0[(size_t)MROWS * CDIM];
__device__ __half             g_a1[(size_t)MROWS * CDIM];

// ---------------- small helpers ----------------
__device__ __forceinline__ int dp4a_us(unsigned int a, unsigned int b, int c) {
    int d; asm("dp4a.u32.s32 %0, %1, %2, %3;" : "=r"(d) : "r"(a), "r"(b), "r"(c));
    return d;
}
__device__ __forceinline__ void mma_f16(float* c, const uint32_t* a, const uint32_t* b) {
    asm volatile(
        "mma.sync.aligned.m16n8k16.row.col.f32.f16.f16.f32 "
        "{%0,%1,%2,%3}, {%4,%5,%6,%7}, {%8,%9}, {%0,%1,%2,%3};"
        : "+f"(c[0]), "+f"(c[1]), "+f"(c[2]), "+f"(c[3])
        : "r"(a[0]), "r"(a[1]), "r"(a[2]), "r"(a[3]), "r"(b[0]), "r"(b[1]));
}
__device__ __forceinline__ uint32_t smem_u32(const void* p) {
    uint32_t a;
    asm("{ .reg .u64 t; cvta.to.shared.u64 t, %1; cvt.u32.u64 %0, t; }" : "=r"(a) : "l"(p));
    return a;
}
__device__ __forceinline__ void cpasync16(uint32_t s, const void* g) {
    asm volatile("cp.async.cg.shared.global [%0], [%1], 16;" :: "r"(s), "l"(g));
}
// NATURAL-scale fp16 2-way splits (R13/R14-validated):
//   A (x ~ O(1)):   x    = a0 + a1
//   W (w ~ 0.02):   32*w = b0 + b1
// x*w = 2^-5*(a0b0 + a0b1 + a1b0) + (a1b1 dropped; QK signs repaired exactly)
__device__ __forceinline__ void hsplitA(float x, __half& s0, __half& s1) {
    s0 = __float2half_rn(x);
    s1 = __float2half_rn(x - __half2float(s0));
}
__device__ __forceinline__ void hsplitB(float w, __half& s0, __half& s1) {
    float ws = w * 32.0f;
    s0 = __float2half_rn(ws);
    s1 = __float2half_rn(ws - __half2float(s0));
}
#define SC_HH 0.03125f                    // 2^-5

// ---------------- split kernels (run once per buffer) ----------------
__global__ __launch_bounds__(256) void split_kernel(
    const float* __restrict__ src, __half* __restrict__ d0, __half* __restrict__ d1,
    int n4, int isB)
{
    int i = blockIdx.x * 256 + threadIdx.x;
    if (i >= n4) return;
    float4 v = *(const float4*)(src + (size_t)i * 4);
    __half h0[4], h1[4];
    if (isB) {
        hsplitB(v.x, h0[0], h1[0]); hsplitB(v.y, h0[1], h1[1]);
        hsplitB(v.z, h0[2], h1[2]); hsplitB(v.w, h0[3], h1[3]);
    } else {
        hsplitA(v.x, h0[0], h1[0]); hsplitA(v.y, h0[1], h1[1]);
        hsplitA(v.z, h0[2], h1[2]); hsplitA(v.w, h0[3], h1[3]);
    }
    *(uint2*)(d0 + (size_t)i * 4) = *(uint2*)h0;
    *(uint2*)(d1 + (size_t)i * 4) = *(uint2*)h1;
}

// ======= cp.async fp16 split-GEMM, single-fragment fp32 drain (R15) =========
// C[M,N] = (A0+A1)[M,768] @ ((B0+B1))[N,768]^T * 2^-5 (+bias), ld = ldc.
// R15: 2-stage cp.async pipeline + __launch_bounds__(256,2) so TWO CTAs
// co-reside per SM (smem 80KB x2 = 160KB <= 228KB; regs capped at 128).
// Cross-CTA interleaving hides barrier/LDS phases that left the tensor pipe
// at 43.6% in R14's single-CTA profile. MMA arithmetic unchanged.
#define TBM   128
#define TBN   128
#define TBK   32
#define STG   2
#define ROWH  40                    // halfs per smem row (32 data + 8 pad)
#define TILEH (128 * ROWH)          // 5120 halfs per tile
#define STAGEH (4 * TILEH)          // A0,A1,B0,B1
#define GSMEM (STG * STAGEH * 2)    // 81,920 B

__global__ void __launch_bounds__(256, 2) gemm_h(
    const __half* __restrict__ A0, const __half* __restrict__ A1,
    const __half* __restrict__ B0, const __half* __restrict__ B1,
    const float* __restrict__ bias, float* __restrict__ C,
    int M, int ldc)
{
    extern __shared__ __half smh[];
    const uint32_t sbyte = smem_u32(smh);

    const int tid  = threadIdx.x;
    const int wid  = tid >> 5;
    const int lane = tid & 31;
    const int gq   = lane >> 2;
    const int tq   = lane & 3;
    const int bm = blockIdx.y * TBM;
    const int bn = blockIdx.x * TBN;
    const int wm = (wid >> 2) * 64;
    const int wn = (wid & 3) * 32;
    const int KT = GK / TBK;        // 24

    // per-thread cp.async mapping: 2 chunks of 16B per tile, 4 tiles
    const int c0 = tid * 2;
    const int row0 = c0 >> 2, col0 = c0 & 3;
    const int row1 = (c0 + 1) >> 2, col1 = (c0 + 1) & 3;
    int ar0 = bm + row0; if (ar0 >= M) ar0 = M - 1;
    int ar1 = bm + row1; if (ar1 >= M) ar1 = M - 1;

    const __half* gsrc[4] = {A0, A1, B0, B1};

    auto issue_stage = [&](int kt) {
        const int k0 = kt * TBK;
        const uint32_t sb = sbyte + (uint32_t)(kt % STG) * STAGEH * 2;
        #pragma unroll
        for (int t = 0; t < 4; ++t) {
            int r0 = (t < 2) ? ar0 : (bn + row0);
            int r1 = (t < 2) ? ar1 : (bn + row1);
            cpasync16(sb + (uint32_t)(t * TILEH + row0 * ROWH + col0 * 8) * 2,
                      gsrc[t] + (size_t)r0 * GK + k0 + col0 * 8);
            cpasync16(sb + (uint32_t)(t * TILEH + row1 * ROWH + col1 * 8) * 2,
                      gsrc[t] + (size_t)r1 * GK + k0 + col1 * 8);
        }
    };

    float acc[4][4][4];
    #pragma unroll
    for (int i = 0; i < 4; i++)
        #pragma unroll
        for (int j = 0; j < 4; j++)
            #pragma unroll
            for (int r = 0; r < 4; r++) acc[i][j][r] = 0.f;

    // prologue: stages 0,1 in flight
    issue_stage(0);
    asm volatile("cp.async.commit_group;" ::: "memory");
    issue_stage(1);
    asm volatile("cp.async.commit_group;" ::: "memory");

    for (int kt = 0; kt < KT; ++kt) {
        asm volatile("cp.async.wait_group %0;" :: "n"(1) : "memory");
        __syncthreads();

        const uint32_t* sp = (const uint32_t*)smh + (size_t)(kt % STG) * STAGEH / 2;
        const uint32_t* at[2] = { sp + 0 * (TILEH/2) + (wm + gq) * (ROWH/2),
                                  sp + 1 * (TILEH/2) + (wm + gq) * (ROWH/2) };
        const uint32_t* bt[2] = { sp + 2 * (TILEH/2) + (wn + gq) * (ROWH/2),
                                  sp + 3 * (TILEH/2) + (wn + gq) * (ROWH/2) };

        #pragma unroll
        for (int kk8 = 0; kk8 < TBK/2; kk8 += 8) {     // two 16-k steps
            uint32_t bf[2][4][2];
            #pragma unroll
            for (int t = 0; t < 2; ++t)
                #pragma unroll
                for (int nt = 0; nt < 4; ++nt) {
                    const uint32_t* bp = bt[t] + nt * 8 * (ROWH/2) + kk8 + tq;
                    bf[t][nt][0] = bp[0];
                    bf[t][nt][1] = bp[4];
                }
            #pragma unroll
            for (int mt = 0; mt < 4; ++mt) {
                uint32_t af[2][4];
                #pragma unroll
                for (int t = 0; t < 2; ++t) {
                    const uint32_t* ap = at[t] + mt * 16 * (ROWH/2) + kk8 + tq;
                    af[t][0] = ap[0];
                    af[t][1] = ap[8 * (ROWH/2)];
                    af[t][2] = ap[4];
                    af[t][3] = ap[8 * (ROWH/2) + 4];
                }
                #pragma unroll
                for (int nt = 0; nt < 4; ++nt) {
                    float d[4] = {0.f, 0.f, 0.f, 0.f};
                    mma_f16(d, af[0], bf[0][nt]);      // a0 b0
                    mma_f16(d, af[0], bf[1][nt]);      // a0 b1
                    mma_f16(d, af[1], bf[0][nt]);      // a1 b0
                    #pragma unroll
                    for (int r = 0; r < 4; ++r)
                        acc[mt][nt][r] = fmaf(d[r], SC_HH, acc[mt][nt][r]);
                }
            }
        }
        // buffer kt%STG fully consumed; safe to refill AFTER barrier
        __syncthreads();
        if (kt + 2 < KT) issue_stage(kt + 2);
        asm volatile("cp.async.commit_group;" ::: "memory");
    }

    // ---- epilogue ----
    #pragma unroll
    for (int mt = 0; mt < 4; ++mt) {
        int r0 = bm + wm + mt * 16 + gq;
        int r1 = r0 + 8;
        #pragma unroll
        for (int nt = 0; nt < 4; ++nt) {
            int c = bn + wn + nt * 8 + tq * 2;
            float b0 = bias ? bias[c]     : 0.f;
            float b1 = bias ? bias[c + 1] : 0.f;
            if (r0 < M) {
                float2 v; v.x = acc[mt][nt][0] + b0; v.y = acc[mt][nt][1] + b1;
                *(float2*)(C + (size_t)r0 * ldc + c) = v;
            }
            if (r1 < M) {
                float2 v; v.x = acc[mt][nt][2] + b0; v.y = acc[mt][nt][3] + b1;
                *(float2*)(C + (size_t)r1 * ldc + c) = v;
            }
        }
    }
}

// ---------------- per-(b,h) |q| / |k| mean scales ----------------
__global__ __launch_bounds__(256) void scales_kernel(const float* __restrict__ qkv)
{
    __shared__ float red[256];
    const int which = blockIdx.x & 1;
    const int bh    = blockIdx.x >> 1;
    const int b = bh / HEADS, h = bh % HEADS;
    const float* base = qkv + (size_t)b * NTOK * CK + which * CDIM + h * HDIM;

    float s = 0.f;
    for (int i = threadIdx.x; i < NTOK * HDIM; i += 256) {
        int n = i >> 6, dd = i & 63;
        s += fabsf(base[(size_t)n * CK + dd]);
    }
    red[threadIdx.x] = s; __syncthreads();
    for (int o = 128; o; o >>= 1) {
        if (threadIdx.x < o) red[threadIdx.x] += red[threadIdx.x + o];
        __syncthreads();
    }
    if (threadIdx.x == 0) {
        float v = red[0] / 12608.0f;
        if (which) g_sk[bh] = v; else g_sq[bh] = v;
    }
}

// ---------------- pack: sign bits (with exact fp32 repair), int8 v ---------
#define REPAIR_TH 1e-4f
__device__ __forceinline__ float exact_dot768(const float* __restrict__ xr,
                                              const float* __restrict__ wr) {
    float s0 = 0.f, s1 = 0.f, s2 = 0.f, s3 = 0.f;
    #pragma unroll 4
    for (int i = 0; i < GK; i += 4) {
        s0 = fmaf(xr[i+0], wr[i+0], s0);
        s1 = fmaf(xr[i+1], wr[i+1], s1);
        s2 = fmaf(xr[i+2], wr[i+2], s2);
        s3 = fmaf(xr[i+3], wr[i+3], s3);
    }
    return (s0 + s1) + (s2 + s3);
}

__global__ __launch_bounds__(256) void pack_kernel(
    const float* __restrict__ qkv,
    const float* __restrict__ x, const float* __restrict__ qkv_w)
{
    const int bh = blockIdx.x;
    const int b = bh / HEADS, h = bh % HEADS;
    const size_t rowbase = (size_t)b * NTOK * CK + h * HDIM;
    const float* qb_ = qkv + rowbase;
    const float* kb_ = qkv + rowbase + CDIM;
    const float* vb_ = qkv + rowbase + 2 * CDIM;

    for (int n = threadIdx.x; n < NTOK; n += 256) {
        const float* qr = qb_ + (size_t)n * CK;
        const float* kr = kb_ + (size_t)n * CK;
        const float* xrow = x + (size_t)(b * NTOK + n) * GK;
        unsigned long long qm = 0ull, km = 0ull;
        #pragma unroll
        for (int c4 = 0; c4 < 16; c4++) {
            float qe[4], ke[4];
            *(float4*)qe = *(const float4*)(qr + c4 * 4);
            *(float4*)ke = *(const float4*)(kr + c4 * 4);
            #pragma unroll
            for (int j = 0; j < 4; j++) {
                int dd = c4 * 4 + j;
                float qv = qe[j];
                if (fabsf(qv) < REPAIR_TH)
                    qv = exact_dot768(xrow, qkv_w + (size_t)(h * HDIM + dd) * GK);
                float kv = ke[j];
                if (fabsf(kv) < REPAIR_TH)
                    kv = exact_dot768(xrow, qkv_w + (size_t)(CDIM + h * HDIM + dd) * GK);
                if (qv > 0.f) qm |= 1ull << dd;
                if (kv > 0.f) km |= 1ull << dd;
            }
        }
        g_qb[bh * NTOK + n] = qm;
        g_kb[bh * NTOK + n] = km;
    }

    const float SV = 2.0f / 127.0f;
    for (int i = threadIdx.x; i < HDIM * NW; i += 256) {
        int dd = i / NW, w = i % NW;
        unsigned int word = 0;
        #pragma unroll
        for (int j = 0; j < 4; j++) {
            int m = 4 * w + j;
            int vi = 0;
            if (m < NTOK) {
                float v = vb_[(size_t)m * CK + dd];
                v = fminf(fmaxf(v, -2.f), 2.f);
                float r = rintf(v / SV);
                r = fminf(fmaxf(r, -127.f), 127.f);
                vi = (int)r;
            }
            word |= ((unsigned)vi & 0xFFu) << (8 * j);
        }
        g_vT[(size_t)bh * HDIM * NW + i] = word;
    }
}

// ---------------- fused binary attention (writes pre-split fp16 att) -------
__global__ __launch_bounds__(256) void attn_kernel(
    const float* __restrict__ rel_table, const int* __restrict__ rel_index)
{
    __shared__ unsigned long long qb_s[NTOK], kb_s[NTOK];
    __shared__ float rel_s[NRD];
    __shared__ unsigned int v_s[HDIM * NW];
    __shared__ __align__(4) unsigned char p_bytes[8 * 224];

    const int bh = blockIdx.x;
    const int b = bh / HEADS, h = bh % HEADS;
    const int tid = threadIdx.x;

    for (int i = tid; i < NTOK; i += 256) {
        qb_s[i] = g_qb[bh * NTOK + i];
        kb_s[i] = g_kb[bh * NTOK + i];
    }
    for (int i = tid; i < NRD; i += 256) rel_s[i] = rel_table[i * HEADS + h];
    for (int i = tid; i < HDIM * NW; i += 256) v_s[i] = g_vT[(size_t)bh * HDIM * NW + i];
    __syncthreads();

    const float sqk = g_sq[bh] * g_sk[bh];
    const float SP  = 1.0f / 255.0f;
    const float OSC = (1.0f / 255.0f) * (2.0f / 127.0f);
    const int warp = tid >> 5, lane = tid & 31;

    for (int n = warp; n < NTOK; n += 8) {
        const unsigned long long qm = qb_s[n];
        const int* ridx = rel_index + n * NTOK;

        float logit[7];
        float mx = -3.0e38f;
        #pragma unroll
        for (int t = 0; t < 7; t++) {
            int m = lane + (t << 5);
            float lg = -3.0e38f;
            if (m < NTOK) {
                int dot = 64 - 2 * __popcll(qm ^ kb_s[m]);
                lg = (sqk * (float)dot) * 0.125f + rel_s[ridx[m]];
            }
            logit[t] = lg;
            mx = fmaxf(mx, lg);
        }
        #pragma unroll
        for (int o = 16; o; o >>= 1) mx = fmaxf(mx, __shfl_xor_sync(0xffffffffu, mx, o));

        float e[7], sum = 0.f;
        #pragma unroll
        for (int t = 0; t < 7; t++) {
            int m = lane + (t << 5);
            e[t] = (m < NTOK) ? expf(logit[t] - mx) : 0.f;
            sum += e[t];
        }
        #pragma unroll
        for (int o = 16; o; o >>= 1) sum += __shfl_xor_sync(0xffffffffu, sum, o);

        unsigned char* pb = p_bytes + warp * 224;
        #pragma unroll
        for (int t = 0; t < 7; t++) {
            int m = lane + (t << 5);
            int pi = 0;
            if (m < NTOK) {
                float p = e[t] / sum;
                float r = rintf(p / SP);
                r = fminf(fmaxf(r, 0.f), 255.f);
                pi = (int)r;
            }
            pb[m] = (unsigned char)pi;
        }
        __syncwarp();

        const unsigned int* pw = (const unsigned int*)pb;
        const unsigned int* v0 = &v_s[lane * NW];
        const unsigned int* v1 = &v_s[(lane + 32) * NW];
        int acc0 = 0, acc1 = 0;
        #pragma unroll
        for (int w = 0; w < NW; w++) {
            unsigned int pword = pw[w];
            acc0 = dp4a_us(pword, v0[w], acc0);
            acc1 = dp4a_us(pword, v1[w], acc1);
        }

        // write pre-split fp16 att planes (same hsplitA arithmetic)
        size_t obase = (size_t)(b * NTOK + n) * CDIM + h * HDIM;
        float va = (float)acc0 * OSC;
        float vb = (float)acc1 * OSC;
        __half a0, a1;
        hsplitA(va, a0, a1);
        g_a0[obase + lane] = a0;
        g_a1[obase + lane] = a1;
        hsplitA(vb, a0, a1);
        g_a0[obase + lane + 32] = a0;
        g_a1[obase + lane + 32] = a1;
        __syncwarp();
    }
}

// ---------------- launcher ----------------
extern "C" void kernel_launch(void* const* d_in, const int* in_sizes, int n_in,
                              void* d_out, int out_size)
{
    const float* x         = (const float*)d_in[0];
    const float* qkv_w     = (const float*)d_in[1];
    const float* proj_w    = (const float*)d_in[2];
    const float* proj_b    = (const float*)d_in[3];
    const float* rel_table = (const float*)d_in[4];
    const int*   rel_index = (const int*)d_in[5];
    float* out = (float*)d_out;

    float *qkv_ptr = nullptr;
    cudaGetSymbolAddress((void**)&qkv_ptr, g_qkv);
    __half *x0, *x1, *w0, *w1, *p0, *p1, *a0, *a1;
    cudaGetSymbolAddress((void**)&x0, g_x0);
    cudaGetSymbolAddress((void**)&x1, g_x1);
    cudaGetSymbolAddress((void**)&w0, g_w0);
    cudaGetSymbolAddress((void**)&w1, g_w1);
    cudaGetSymbolAddress((void**)&p0, g_p0);
    cudaGetSymbolAddress((void**)&p1, g_p1);
    cudaGetSymbolAddress((void**)&a0, g_a0);
    cudaGetSymbolAddress((void**)&a1, g_a1);

    cudaFuncSetAttribute(gemm_h, cudaFuncAttributeMaxDynamicSharedMemorySize, GSMEM);

    // 0) pre-split inputs to fp16 planes
    {
        int n4 = MROWS * GK / 4;
        split_kernel<<<(n4 + 255) / 256, 256>>>(x, x0, x1, n4, 0);
        n4 = CK * GK / 4;
        split_kernel<<<(n4 + 255) / 256, 256>>>(qkv_w, w0, w1, n4, 1);
        n4 = CDIM * GK / 4;
        split_kernel<<<(n4 + 255) / 256, 256>>>(proj_w, p0, p1, n4, 1);
    }

    const int GY = (MROWS + TBM - 1) / TBM;  // 99

    // 1) qkv = x @ qkv_w^T  (cp.async fp16 split-GEMM, 2 CTAs/SM)
    dim3 g1(CK / TBN, GY);
    gemm_h<<<g1, 256, GSMEM>>>(x0, x1, w0, w1, nullptr, qkv_ptr, MROWS, CK);

    // 2) per-(b,h) scales for q,k
    scales_kernel<<<BHT * 2, 256>>>(qkv_ptr);

    // 3) sign-pack q,k (with exact fp32 repair near zero); int8 v
    pack_kernel<<<BHT, 256>>>(qkv_ptr, x, qkv_w);

    // 4) fused binary attention -> pre-split fp16 att planes
    attn_kernel<<<BHT, 256>>>(rel_table, rel_index);

    // 5) out = att @ proj_w^T + proj_b
    dim3 gp(CDIM / TBN, GY);
    gemm_h<<<gp, 256, GSMEM>>>(a0, a1, p0, p1, proj_b, out, MROWS, CDIM);
}

// round 16
// speedup vs baseline: 1.5938x; 1.0350x over previous
#include <cuda_runtime.h>
#include <cuda_fp16.h>
#include <cstdint>

// ---------------- problem constants ----------------
#define BATCH 64
#define NTOK  197
#define HEADS 12
#define HDIM  64
#define CDIM  768
#define CK    2304
#define MROWS (BATCH*NTOK) // 12608
#define NRD   732
#define NW    50
#define BHT   (BATCH*HEADS)
#define GK    768

// ---------------- device scratch (cudaMalloc is banned) -------------
__device__ float              g_qkv[(size_t)MROWS * CK];
__device__ float              g_sq[BHT];
__device__ float              g_sk[BHT];
__device__ unsigned long long g_qb[BHT * NTOK];
__device__ unsigned long long g_kb[BHT * NTOK];
__device__ unsigned int       g_vT[(size_t)BHT * HDIM * NW];
// pre-split fp16 planes
__device__ __half             g_x0[(size_t)MROWS * GK];
__device__ __half             g_x1[(size_t)MROWS * GK];
__device__ __half             g_w0[(size_t)CK * GK];
__device__ __half             g_w1[(size_t)CK * GK];
__device__ __half             g_p0[(size_t)CDIM * GK];
__device__ __half             g_p1[(size_t)CDIM * GK];
__device__ __half             g_a0[(size_t)MROWS * CDIM];
__device__ __half             g_a1[(size_t)MROWS * CDIM];

// ---------------- small helpers ----------------
__device__ __forceinline__ int dp4a_us(unsigned int a, unsigned int b, int c) {
    int d; asm("dp4a.u32.s32 %0, %1, %2, %3;" : "=r"(d) : "r"(a), "r"(b), "r"(c));
    return d;
}
__device__ __forceinline__ void mma_f16(float* c, const uint32_t* a, const uint32_t* b) {
    asm volatile(
        "mma.sync.aligned.m16n8k16.row.col.f32.f16.f16.f32 "
        "{%0,%1,%2,%3}, {%4,%5,%6,%7}, {%8,%9}, {%0,%1,%2,%3};"
        : "+f"(c[0]), "+f"(c[1]), "+f"(c[2]), "+f"(c[3])
        : "r"(a[0]), "r"(a[1]), "r"(a[2]), "r"(a[3]), "r"(b[0]), "r"(b[1]));
}
#define LDSM4(r0, r1, r2, r3, addr) \
    asm volatile("ldmatrix.sync.aligned.m8n8.x4.shared.b16 {%0,%1,%2,%3}, [%4];" \
        : "=r"(r0), "=r"(r1), "=r"(r2), "=r"(r3) : "r"(addr))
__device__ __forceinline__ uint32_t smem_u32(const void* p) {
    uint32_t a;
    asm("{ .reg .u64 t; cvta.to.shared.u64 t, %1; cvt.u32.u64 %0, t; }" : "=r"(a) : "l"(p));
    return a;
}
__device__ __forceinline__ void cpasync16(uint32_t s, const void* g) {
    asm volatile("cp.async.cg.shared.global [%0], [%1], 16;" :: "r"(s), "l"(g));
}
// NATURAL-scale fp16 2-way splits (R13/R14-validated):
//   A (x ~ O(1)):   x    = a0 + a1
//   W (w ~ 0.02):   32*w = b0 + b1
// x*w = 2^-5*(a0b0 + a0b1 + a1b0) + (a1b1 dropped; QK signs repaired exactly)
__device__ __forceinline__ void hsplitA(float x, __half& s0, __half& s1) {
    s0 = __float2half_rn(x);
    s1 = __float2half_rn(x - __half2float(s0));
}
__device__ __forceinline__ void hsplitB(float w, __half& s0, __half& s1) {
    float ws = w * 32.0f;
    s0 = __float2half_rn(ws);
    s1 = __float2half_rn(ws - __half2float(s0));
}
#define SC_HH 0.03125f                    // 2^-5

// ---------------- split kernels (run once per buffer) ----------------
__global__ __launch_bounds__(256) void split_kernel(
    const float* __restrict__ src, __half* __restrict__ d0, __half* __restrict__ d1,
    int n4, int isB)
{
    int i = blockIdx.x * 256 + threadIdx.x;
    if (i >= n4) return;
    float4 v = *(const float4*)(src + (size_t)i * 4);
    __half h0[4], h1[4];
    if (isB) {
        hsplitB(v.x, h0[0], h1[0]); hsplitB(v.y, h0[1], h1[1]);
        hsplitB(v.z, h0[2], h1[2]); hsplitB(v.w, h0[3], h1[3]);
    } else {
        hsplitA(v.x, h0[0], h1[0]); hsplitA(v.y, h0[1], h1[1]);
        hsplitA(v.z, h0[2], h1[2]); hsplitA(v.w, h0[3], h1[3]);
    }
    *(uint2*)(d0 + (size_t)i * 4) = *(uint2*)h0;
    *(uint2*)(d1 + (size_t)i * 4) = *(uint2*)h1;
}

// ======= cp.async fp16 split-GEMM, ldmatrix fragments (R16) =================
// C[M,N] = (A0+A1)[M,768] @ ((B0+B1))[N,768]^T * 2^-5 (+bias), ld = ldc.
// R16: fragment loads via ldmatrix.x4 (12 LDSM vs 48 LDS.32 per warp per 16-k
// step) — removes the LSU/scoreboard stalls that capped tensor at 48%.
// Arithmetic (fragments, op order) bit-identical to R15.
#define TBM   128
#define TBN   128
#define TBK   32
#define STG   2
#define ROWH  40                    // halfs per smem row (32 data + 8 pad)
#define TILEH (128 * ROWH)          // 5120 halfs per tile
#define STAGEH (4 * TILEH)          // A0,A1,B0,B1
#define GSMEM (STG * STAGEH * 2)    // 81,920 B

__global__ void __launch_bounds__(256, 2) gemm_h(
    const __half* __restrict__ A0, const __half* __restrict__ A1,
    const __half* __restrict__ B0, const __half* __restrict__ B1,
    const float* __restrict__ bias, float* __restrict__ C,
    int M, int ldc)
{
    extern __shared__ __half smh[];
    const uint32_t sbyte = smem_u32(smh);

    const int tid  = threadIdx.x;
    const int wid  = tid >> 5;
    const int lane = tid & 31;
    const int gq   = lane >> 2;
    const int tq   = lane & 3;
    const int bm = blockIdx.y * TBM;
    const int bn = blockIdx.x * TBN;
    const int wm = (wid >> 2) * 64;
    const int wn = (wid & 3) * 32;
    const int KT = GK / TBK;        // 24

    // ---- cp.async producer mapping (unchanged from R15) ----
    const int c0 = tid * 2;
    const int row0 = c0 >> 2, col0 = c0 & 3;
    const int row1 = (c0 + 1) >> 2, col1 = (c0 + 1) & 3;
    int ar0 = bm + row0; if (ar0 >= M) ar0 = M - 1;
    int ar1 = bm + row1; if (ar1 >= M) ar1 = M - 1;
    const __half* gsrc[4] = {A0, A1, B0, B1};

    auto issue_stage = [&](int kt) {
        const int k0 = kt * TBK;
        const uint32_t sb = sbyte + (uint32_t)(kt % STG) * STAGEH * 2;
        #pragma unroll
        for (int t = 0; t < 4; ++t) {
            int r0 = (t < 2) ? ar0 : (bn + row0);
            int r1 = (t < 2) ? ar1 : (bn + row1);
            cpasync16(sb + (uint32_t)(t * TILEH + row0 * ROWH + col0 * 8) * 2,
                      gsrc[t] + (size_t)r0 * GK + k0 + col0 * 8);
            cpasync16(sb + (uint32_t)(t * TILEH + row1 * ROWH + col1 * 8) * 2,
                      gsrc[t] + (size_t)r1 * GK + k0 + col1 * 8);
        }
    };

    // ---- ldmatrix per-lane address offsets (bytes within a stage) ----
    // A tiles (x4 -> m16k16): m0=rows0-7/k0-7, m1=rows8-15/k0-7, m2=rows0-7/k8-15, m3=rows8-15/k8-15
    const int rowA  = (lane < 16) ? lane : (lane - 16);
    const int colA8 = (lane >= 16) ? 8 : 0;
    // B tiles (x4 -> two n8k16 frags): m0/m1 = nt(2p) k0-7/k8-15, m2/m3 = nt(2p+1)
    const int rowB  = (lane & 7) + ((lane >= 16) ? 8 : 0);
    const int colB8 = (lane & 8) ? 8 : 0;
    uint32_t aoff[2][4], boff[2][2];
    #pragma unroll
    for (int t = 0; t < 2; ++t) {
        #pragma unroll
        for (int mt = 0; mt < 4; ++mt)
            aoff[t][mt] = (uint32_t)((t * TILEH + (wm + mt * 16 + rowA) * ROWH
                                      + colA8) * 2);
        #pragma unroll
        for (int p = 0; p < 2; ++p)
            boff[t][p] = (uint32_t)(((2 + t) * TILEH + (wn + p * 16 + rowB) * ROWH
                                      + colB8) * 2);
    }

    float acc[4][4][4];
    #pragma unroll
    for (int i = 0; i < 4; i++)
        #pragma unroll
        for (int j = 0; j < 4; j++)
            #pragma unroll
            for (int r = 0; r < 4; r++) acc[i][j][r] = 0.f;

    issue_stage(0);
    asm volatile("cp.async.commit_group;" ::: "memory");
    issue_stage(1);
    asm volatile("cp.async.commit_group;" ::: "memory");

    for (int kt = 0; kt < KT; ++kt) {
        asm volatile("cp.async.wait_group %0;" :: "n"(1) : "memory");
        __syncthreads();

        const uint32_t stb = sbyte + (uint32_t)(kt % STG) * STAGEH * 2;

        #pragma unroll
        for (int s = 0; s < 2; ++s) {                  // two 16-k steps
            const uint32_t so = stb + (uint32_t)s * 32; // 16 halfs = 32 bytes
            // B fragments: 2 terms x 4 n-tiles via 4 LDSM.x4
            uint32_t bf[2][4][2];
            #pragma unroll
            for (int t = 0; t < 2; ++t)
                #pragma unroll
                for (int p = 0; p < 2; ++p)
                    LDSM4(bf[t][2*p][0], bf[t][2*p][1],
                          bf[t][2*p+1][0], bf[t][2*p+1][1], so + boff[t][p]);
            #pragma unroll
            for (int mt = 0; mt < 4; ++mt) {
                uint32_t af[2][4];
                LDSM4(af[0][0], af[0][1], af[0][2], af[0][3], so + aoff[0][mt]);
                LDSM4(af[1][0], af[1][1], af[1][2], af[1][3], so + aoff[1][mt]);
                #pragma unroll
                for (int nt = 0; nt < 4; ++nt) {
                    float d[4] = {0.f, 0.f, 0.f, 0.f};
                    mma_f16(d, af[0], bf[0][nt]);      // a0 b0
                    mma_f16(d, af[0], bf[1][nt]);      // a0 b1
                    mma_f16(d, af[1], bf[0][nt]);      // a1 b0
                    #pragma unroll
                    for (int r = 0; r < 4; ++r)
                        acc[mt][nt][r] = fmaf(d[r], SC_HH, acc[mt][nt][r]);
                }
            }
        }
        __syncthreads();
        if (kt + 2 < KT) issue_stage(kt + 2);
        asm volatile("cp.async.commit_group;" ::: "memory");
    }

    // ---- epilogue ----
    #pragma unroll
    for (int mt = 0; mt < 4; ++mt) {
        int r0 = bm + wm + mt * 16 + gq;
        int r1 = r0 + 8;
        #pragma unroll
        for (int nt = 0; nt < 4; ++nt) {
            int c = bn + wn + nt * 8 + tq * 2;
            float b0 = bias ? bias[c]     : 0.f;
            float b1 = bias ? bias[c + 1] : 0.f;
            if (r0 < M) {
                float2 v; v.x = acc[mt][nt][0] + b0; v.y = acc[mt][nt][1] + b1;
                *(float2*)(C + (size_t)r0 * ldc + c) = v;
            }
            if (r1 < M) {
                float2 v; v.x = acc[mt][nt][2] + b0; v.y = acc[mt][nt][3] + b1;
                *(float2*)(C + (size_t)r1 * ldc + c) = v;
            }
        }
    }
}

// ---------------- per-(b,h) |q| / |k| mean scales ----------------
__global__ __launch_bounds__(256) void scales_kernel(const float* __restrict__ qkv)
{
    __shared__ float red[256];
    const int which = blockIdx.x & 1;
    const int bh    = blockIdx.x >> 1;
    const int b = bh / HEADS, h = bh % HEADS;
    const float* base = qkv + (size_t)b * NTOK * CK + which * CDIM + h * HDIM;

    float s = 0.f;
    for (int i = threadIdx.x; i < NTOK * HDIM; i += 256) {
        int n = i >> 6, dd = i & 63;
        s += fabsf(base[(size_t)n * CK + dd]);
    }
    red[threadIdx.x] = s; __syncthreads();
    for (int o = 128; o; o >>= 1) {
        if (threadIdx.x < o) red[threadIdx.x] += red[threadIdx.x + o];
        __syncthreads();
    }
    if (threadIdx.x == 0) {
        float v = red[0] / 12608.0f;
        if (which) g_sk[bh] = v; else g_sq[bh] = v;
    }
}

// ---------------- pack: sign bits (with exact fp32 repair), int8 v ---------
#define REPAIR_TH 1e-4f
__device__ __forceinline__ float exact_dot768(const float* __restrict__ xr,
                                              const float* __restrict__ wr) {
    float s0 = 0.f, s1 = 0.f, s2 = 0.f, s3 = 0.f;
    #pragma unroll 4
    for (int i = 0; i < GK; i += 4) {
        s0 = fmaf(xr[i+0], wr[i+0], s0);
        s1 = fmaf(xr[i+1], wr[i+1], s1);
        s2 = fmaf(xr[i+2], wr[i+2], s2);
        s3 = fmaf(xr[i+3], wr[i+3], s3);
    }
    return (s0 + s1) + (s2 + s3);
}

__global__ __launch_bounds__(256) void pack_kernel(
    const float* __restrict__ qkv,
    const float* __restrict__ x, const float* __restrict__ qkv_w)
{
    const int bh = blockIdx.x;
    const int b = bh / HEADS, h = bh % HEADS;
    const size_t rowbase = (size_t)b * NTOK * CK + h * HDIM;
    const float* qb_ = qkv + rowbase;
    const float* kb_ = qkv + rowbase + CDIM;
    const float* vb_ = qkv + rowbase + 2 * CDIM;

    for (int n = threadIdx.x; n < NTOK; n += 256) {
        const float* qr = qb_ + (size_t)n * CK;
        const float* kr = kb_ + (size_t)n * CK;
        const float* xrow = x + (size_t)(b * NTOK + n) * GK;
        unsigned long long qm = 0ull, km = 0ull;
        #pragma unroll
        for (int c4 = 0; c4 < 16; c4++) {
            float qe[4], ke[4];
            *(float4*)qe = *(const float4*)(qr + c4 * 4);
            *(float4*)ke = *(const float4*)(kr + c4 * 4);
            #pragma unroll
            for (int j = 0; j < 4; j++) {
                int dd = c4 * 4 + j;
                float qv = qe[j];
                if (fabsf(qv) < REPAIR_TH)
                    qv = exact_dot768(xrow, qkv_w + (size_t)(h * HDIM + dd) * GK);
                float kv = ke[j];
                if (fabsf(kv) < REPAIR_TH)
                    kv = exact_dot768(xrow, qkv_w + (size_t)(CDIM + h * HDIM + dd) * GK);
                if (qv > 0.f) qm |= 1ull << dd;
                if (kv > 0.f) km |= 1ull << dd;
            }
        }
        g_qb[bh * NTOK + n] = qm;
        g_kb[bh * NTOK + n] = km;
    }

    const float SV = 2.0f / 127.0f;
    for (int i = threadIdx.x; i < HDIM * NW; i += 256) {
        int dd = i / NW, w = i % NW;
        unsigned int word = 0;
        #pragma unroll
        for (int j = 0; j < 4; j++) {
            int m = 4 * w + j;
            int vi = 0;
            if (m < NTOK) {
                float v = vb_[(size_t)m * CK + dd];
                v = fminf(fmaxf(v, -2.f), 2.f);
                float r = rintf(v / SV);
                r = fminf(fmaxf(r, -127.f), 127.f);
                vi = (int)r;
            }
            word |= ((unsigned)vi & 0xFFu) << (8 * j);
        }
        g_vT[(size_t)bh * HDIM * NW + i] = word;
    }
}

// ---------------- fused binary attention (writes pre-split fp16 att) -------
__global__ __launch_bounds__(256) void attn_kernel(
    const float* __restrict__ rel_table, const int* __restrict__ rel_index)
{
    __shared__ unsigned long long qb_s[NTOK], kb_s[NTOK];
    __shared__ float rel_s[NRD];
    __shared__ unsigned int v_s[HDIM * NW];
    __shared__ __align__(4) unsigned char p_bytes[8 * 224];

    const int bh = blockIdx.x;
    const int b = bh / HEADS, h = bh % HEADS;
    const int tid = threadIdx.x;

    for (int i = tid; i < NTOK; i += 256) {
        qb_s[i] = g_qb[bh * NTOK + i];
        kb_s[i] = g_kb[bh * NTOK + i];
    }
    for (int i = tid; i < NRD; i += 256) rel_s[i] = rel_table[i * HEADS + h];
    for (int i = tid; i < HDIM * NW; i += 256) v_s[i] = g_vT[(size_t)bh * HDIM * NW + i];
    __syncthreads();

    const float sqk = g_sq[bh] * g_sk[bh];
    const float SP  = 1.0f / 255.0f;
    const float OSC = (1.0f / 255.0f) * (2.0f / 127.0f);
    const int warp = tid >> 5, lane = tid & 31;

    for (int n = warp; n < NTOK; n += 8) {
        const unsigned long long qm = qb_s[n];
        const int* ridx = rel_index + n * NTOK;

        float logit[7];
        float mx = -3.0e38f;
        #pragma unroll
        for (int t = 0; t < 7; t++) {
            int m = lane + (t << 5);
            float lg = -3.0e38f;
            if (m < NTOK) {
                int dot = 64 - 2 * __popcll(qm ^ kb_s[m]);
                lg = (sqk * (float)dot) * 0.125f + rel_s[ridx[m]];
            }
            logit[t] = lg;
            mx = fmaxf(mx, lg);
        }
        #pragma unroll
        for (int o = 16; o; o >>= 1) mx = fmaxf(mx, __shfl_xor_sync(0xffffffffu, mx, o));

        float e[7], sum = 0.f;
        #pragma unroll
        for (int t = 0; t < 7; t++) {
            int m = lane + (t << 5);
            e[t] = (m < NTOK) ? expf(logit[t] - mx) : 0.f;
            sum += e[t];
        }
        #pragma unroll
        for (int o = 16; o; o >>= 1) sum += __shfl_xor_sync(0xffffffffu, sum, o);

        unsigned char* pb = p_bytes + warp * 224;
        #pragma unroll
        for (int t = 0; t < 7; t++) {
            int m = lane + (t << 5);
            int pi = 0;
            if (m < NTOK) {
                float p = e[t] / sum;
                float r = rintf(p / SP);
                r = fminf(fmaxf(r, 0.f), 255.f);
                pi = (int)r;
            }
            pb[m] = (unsigned char)pi;
        }
        __syncwarp();

        const unsigned int* pw = (const unsigned int*)pb;
        const unsigned int* v0 = &v_s[lane * NW];
        const unsigned int* v1 = &v_s[(lane + 32) * NW];
        int acc0 = 0, acc1 = 0;
        #pragma unroll
        for (int w = 0; w < NW; w++) {
            unsigned int pword = pw[w];
            acc0 = dp4a_us(pword, v0[w], acc0);
            acc1 = dp4a_us(pword, v1[w], acc1);
        }

        size_t obase = (size_t)(b * NTOK + n) * CDIM + h * HDIM;
        float va = (float)acc0 * OSC;
        float vb = (float)acc1 * OSC;
        __half a0, a1;
        hsplitA(va, a0, a1);
        g_a0[obase + lane] = a0;
        g_a1[obase + lane] = a1;
        hsplitA(vb, a0, a1);
        g_a0[obase + lane + 32] = a0;
        g_a1[obase + lane + 32] = a1;
        __syncwarp();
    }
}

// ---------------- launcher ----------------
extern "C" void kernel_launch(void* const* d_in, const int* in_sizes, int n_in,
                              void* d_out, int out_size)
{
    const float* x         = (const float*)d_in[0];
    const float* qkv_w     = (const float*)d_in[1];
    const float* proj_w    = (const float*)d_in[2];
    const float* proj_b    = (const float*)d_in[3];
    const float* rel_table = (const float*)d_in[4];
    const int*   rel_index = (const int*)d_in[5];
    float* out = (float*)d_out;

    float *qkv_ptr = nullptr;
    cudaGetSymbolAddress((void**)&qkv_ptr, g_qkv);
    __half *x0, *x1, *w0, *w1, *p0, *p1, *a0, *a1;
    cudaGetSymbolAddress((void**)&x0, g_x0);
    cudaGetSymbolAddress((void**)&x1, g_x1);
    cudaGetSymbolAddress((void**)&w0, g_w0);
    cudaGetSymbolAddress((void**)&w1, g_w1);
    cudaGetSymbolAddress((void**)&p0, g_p0);
    cudaGetSymbolAddress((void**)&p1, g_p1);
    cudaGetSymbolAddress((void**)&a0, g_a0);
    cudaGetSymbolAddress((void**)&a1, g_a1);

    cudaFuncSetAttribute(gemm_h, cudaFuncAttributeMaxDynamicSharedMemorySize, GSMEM);

    // 0) pre-split inputs to fp16 planes
    {
        int n4 = MROWS * GK / 4;
        split_kernel<<<(n4 + 255) / 256, 256>>>(x, x0, x1, n4, 0);
        n4 = CK * GK / 4;
        split_kernel<<<(n4 + 255) / 256, 256>>>(qkv_w, w0, w1, n4, 1);
        n4 = CDIM * GK / 4;
        split_kernel<<<(n4 + 255) / 256, 256>>>(proj_w, p0, p1, n4, 1);
    }

    const int GY = (MROWS + TBM - 1) / TBM;  // 99

    // 1) qkv = x @ qkv_w^T  (ldmatrix fp16 split-GEMM, 2 CTAs/SM)
    dim3 g1(CK / TBN, GY);
    gemm_h<<<g1, 256, GSMEM>>>(x0, x1, w0, w1, nullptr, qkv_ptr, MROWS, CK);

    // 2) per-(b,h) scales for q,k
    scales_kernel<<<BHT * 2, 256>>>(qkv_ptr);

    // 3) sign-pack q,k (with exact fp32 repair near zero); int8 v
    pack_kernel<<<BHT, 256>>>(qkv_ptr, x, qkv_w);

    // 4) fused binary attention -> pre-split fp16 att planes
    attn_kernel<<<BHT, 256>>>(rel_table, rel_index);

    // 5) out = att @ proj_w^T + proj_b
    dim3 gp(CDIM / TBN, GY);
    gemm_h<<<gp, 256, GSMEM>>>(a0, a1, p0, p1, proj_b, out, MROWS, CDIM);
}